// round 7
// baseline (speedup 1.0000x reference)
#include <cuda_runtime.h>
#include <cuda_bf16.h>
#include <cstdint>

// ---------------- problem constants ----------------
#define BN 2
#define NN 16384
#define BKS 136           // bf16 tile row stride (elements): 272 bytes, conflict-free ldmatrix
#define GRID_P 296        // persistent grid: 148 SMs x 2 CTAs
#define N_TILES_G (BN * NN / 32)    // 1024 grad tiles (32 points x 4 nbrs = 128 rows)
#define N_TILES_P (BN * NN / 128)   // 256 precompute tiles (128 rows)

// ---------------- device scratch ----------------
__device__ __align__(256) float g_gW0[BN * NN * 128];              // feat @ W0[3:] + b0
__device__ __align__(256) float g_grad[BN * NN * 4 * 3];           // per-(n,k) grad_pred
__device__ __align__(256) __nv_bfloat16 g_Wb[2 * 128 * BKS];       // Wb^T bf16, padded
__device__ __align__(256) __nv_bfloat16 g_Wf2T[128 * BKS];         // Wf2^T bf16
__device__ __align__(256) __nv_bfloat16 g_W03T[128 * BKS];         // (W0[3:])^T bf16
__device__ unsigned g_ctr[4];                                      // per-step tile counters

// ================= helpers =================
__device__ __forceinline__ uint32_t smem_u32(const void* p) {
    uint32_t a;
    asm("{ .reg .u64 t; cvta.to.shared.u64 t, %1; cvt.u32.u64 %0, t; }" : "=r"(a) : "l"(p));
    return a;
}
__device__ __forceinline__ void ldsm4(uint32_t r[4], uint32_t addr) {
    asm volatile("ldmatrix.sync.aligned.m8n8.x4.shared.b16 {%0,%1,%2,%3}, [%4];"
                 : "=r"(r[0]), "=r"(r[1]), "=r"(r[2]), "=r"(r[3]) : "r"(addr));
}
__device__ __forceinline__ void mma_bf16(float d[4], const uint32_t a[4],
                                         uint32_t b0, uint32_t b1) {
    asm volatile(
        "mma.sync.aligned.m16n8k16.row.col.f32.bf16.bf16.f32 "
        "{%0,%1,%2,%3}, {%4,%5,%6,%7}, {%8,%9}, {%0,%1,%2,%3};"
        : "+f"(d[0]), "+f"(d[1]), "+f"(d[2]), "+f"(d[3])
        : "r"(a[0]), "r"(a[1]), "r"(a[2]), "r"(a[3]), "r"(b0), "r"(b1));
}

// warp-level 128x128x128 GEMM: A frags from aAddr (16 rows/warp slice), full 128-col B
__device__ __forceinline__ void warp_gemm(uint32_t aAddr, uint32_t bAddr, float acc[16][4]) {
#pragma unroll
    for (int j = 0; j < 16; ++j)
#pragma unroll
        for (int i = 0; i < 4; ++i) acc[j][i] = 0.f;
#pragma unroll
    for (int s = 0; s < 8; ++s) {
        uint32_t a[4];
        ldsm4(a, aAddr + s * 32);
#pragma unroll
        for (int jp = 0; jp < 8; ++jp) {
            uint32_t bf[4];
            ldsm4(bf, bAddr + (uint32_t)(jp * 16 * (BKS * 2)) + s * 32);
            mma_bf16(acc[2 * jp],     a, bf[0], bf[1]);
            mma_bf16(acc[2 * jp + 1], a, bf[2], bf[3]);
        }
    }
}

// ================= convert: weights -> bf16 transposed/padded; reset counters =================
__global__ void convert_w_kernel(const float* __restrict__ Wb,
                                 const float* __restrict__ Wf2,
                                 const float* __restrict__ W0)
{
    int idx = blockIdx.x * blockDim.x + threadIdx.x;
    if (idx < 4) g_ctr[idx] = 0;             // reset tile counters for this graph replay
    if (idx >= 4 * 128 * 128) return;
    int seg = idx >> 14;
    int rem = idx & 16383;
    int n = rem >> 7, k = rem & 127;
    if (seg < 2) {
        g_Wb[seg * 128 * BKS + n * BKS + k] = __float2bfloat16(Wb[seg * 16384 + k * 128 + n]);
    } else if (seg == 2) {
        g_Wf2T[n * BKS + k] = __float2bfloat16(Wf2[k * 128 + n]);
    } else {
        g_W03T[n * BKS + k] = __float2bfloat16(W0[(3 + k) * 128 + n]);
    }
}

// ================= shared SMEM layout =================
#define A_BYTES   (128 * BKS * 2)           // 34816
#define B_BYTES   (2 * 128 * BKS * 2)       // 69632
#define MISC_BYTES 4352                     // 1024 floats for W-arrays + sNext slot + pad
#define GK_SMEM   (A_BYTES + B_BYTES + MISC_BYTES)   // 108800 -> 2 CTAs/SM (217600 < 228KB)

// ================= precompute via mma (persistent, static schedule) =================
__global__ __launch_bounds__(256, 2)
void precompute_mma(const float* __restrict__ pcl,
                    const float* __restrict__ Wf1, const float* __restrict__ bf1,
                    const float* __restrict__ bf2, const float* __restrict__ b0,
                    float* __restrict__ out)
{
    extern __shared__ __align__(256) char smc[];
    const int t    = threadIdx.x;
    const int lane = t & 31;
    const int w    = t >> 5;

    char* A_s = smc;
    char* B_s = smc + A_BYTES;
    float* shWf1 = (float*)(smc + A_BYTES + B_BYTES);
    float* shbf1 = shWf1 + 384;
    float* shbf2 = shbf1 + 128;
    float* shb0  = shbf2 + 128;

    for (int i = t; i < 384; i += 256) shWf1[i] = Wf1[i];
    if (t < 128) { shbf1[t] = bf1[t]; shbf2[t] = bf2[t]; shb0[t] = b0[t]; }
    {
        const uint4* s1 = (const uint4*)g_Wf2T;
        const uint4* s2 = (const uint4*)g_W03T;
        uint4* d1 = (uint4*)B_s;
        uint4* d2 = (uint4*)(B_s + A_BYTES);
        for (int i = t; i < A_BYTES / 16; i += 256) { d1[i] = s1[i]; d2[i] = s2[i]; }
    }
    __syncthreads();

    const uint32_t Abase = smem_u32(A_s);
    const uint32_t Bbase = smem_u32(B_s);
    const int mrow = w * 16;
    const int rgrp = lane >> 2;
    const int cpos = (lane & 3) * 2;
    const uint32_t aAddr = Abase
        + (uint32_t)((mrow + (lane & 7) + (((lane >> 3) & 1) << 3)) * (BKS * 2))
        + (uint32_t)(((lane >> 4) << 3) * 2);
    const uint32_t bAddr = Bbase
        + (uint32_t)(((lane & 7) + ((lane >> 4) << 3)) * (BKS * 2))
        + (uint32_t)(((lane >> 3) & 1) << 4);

    for (int tile = blockIdx.x; tile < N_TILES_P; tile += GRID_P) {
        int b  = tile / (NN / 128);
        int n0 = (tile % (NN / 128)) * 128;
        const float* pclb = pcl + ((size_t)b * NN + n0) * 3;
        float* outb = out + ((size_t)b * NN + n0) * 3;

        for (int i = t; i < 128 * 3; i += 256) outb[i] = pclb[i];

        // h1 = relu(pcl @ Wf1 + bf1) -> A_s bf16
        {
            int r = t & 127, half = t >> 7;
            float x0 = pclb[r * 3 + 0], x1 = pclb[r * 3 + 1], x2 = pclb[r * 3 + 2];
#pragma unroll 8
            for (int j = half * 64; j < half * 64 + 64; j += 2) {
                float v0 = fmaf(x0, shWf1[j],     fmaf(x1, shWf1[128 + j],     fmaf(x2, shWf1[256 + j],     shbf1[j])));
                float v1 = fmaf(x0, shWf1[j + 1], fmaf(x1, shWf1[128 + j + 1], fmaf(x2, shWf1[256 + j + 1], shbf1[j + 1])));
                *(__nv_bfloat162*)(A_s + r * (BKS * 2) + j * 2) =
                    __floats2bfloat162_rn(fmaxf(v0, 0.f), fmaxf(v1, 0.f));
            }
        }
        __syncthreads();

        float acc[16][4];

        // GEMM1: feat = h1 @ Wf2 + bf2 (no relu) -> A_s bf16
        warp_gemm(aAddr, bAddr, acc);
        __syncthreads();
#pragma unroll
        for (int j = 0; j < 16; ++j) {
            int c = j * 8 + cpos;
            float b0v = shbf2[c], b1v = shbf2[c + 1];
            *(__nv_bfloat162*)(A_s + (mrow + rgrp) * (BKS * 2) + c * 2) =
                __floats2bfloat162_rn(acc[j][0] + b0v, acc[j][1] + b1v);
            *(__nv_bfloat162*)(A_s + (mrow + rgrp + 8) * (BKS * 2) + c * 2) =
                __floats2bfloat162_rn(acc[j][2] + b0v, acc[j][3] + b1v);
        }
        __syncthreads();

        // GEMM2: gW0 = feat @ W0[3:] + b0 -> global fp32
        warp_gemm(aAddr, bAddr + (uint32_t)A_BYTES, acc);
        {
            float* gb = g_gW0 + ((size_t)b * NN + n0) * 128;
#pragma unroll
            for (int j = 0; j < 16; ++j) {
                int c = j * 8 + cpos;
                float b0v = shb0[c], b1v = shb0[c + 1];
                *(float2*)(gb + (size_t)(mrow + rgrp) * 128 + c) =
                    make_float2(acc[j][0] + b0v, acc[j][1] + b1v);
                *(float2*)(gb + (size_t)(mrow + rgrp + 8) * 128 + c) =
                    make_float2(acc[j][2] + b0v, acc[j][3] + b1v);
            }
        }
        __syncthreads();
    }
}

// ================= grad kernel: persistent, dynamic tile scheduling =================
__global__ __launch_bounds__(256, 2)
void grad_kernel_mma(const float* __restrict__ pcl_noisy, const float* __restrict__ pcl_cur,
                     const float* __restrict__ W0, const float* __restrict__ bb,
                     const float* __restrict__ Wo, const float* __restrict__ bo,
                     int step)
{
    extern __shared__ __align__(256) char smc[];
    const int t    = threadIdx.x;
    const int lane = t & 31;
    const int w    = t >> 5;

    char* A_s = smc;
    char* B_s = smc + A_BYTES;
    float* shW0 = (float*)(smc + A_BYTES + B_BYTES);
    float* shWo = shW0 + 384;
    float* shBB = shWo + 384;
    unsigned* sNext = (unsigned*)(shBB + 256);   // within MISC (1024 floats used, 1088 avail)

    for (int i = t; i < 384; i += 256) { shW0[i] = W0[i]; shWo[i] = Wo[i]; }
    if (t < 256) shBB[t] = bb[t];
    {
        const uint4* src = (const uint4*)g_Wb;
        uint4* dst = (uint4*)B_s;
        for (int i = t; i < B_BYTES / 16; i += 256) dst[i] = src[i];
    }
    if (t == 0) sNext[0] = atomicAdd(&g_ctr[step], 1u);
    __syncthreads();

    const uint32_t Abase = smem_u32(A_s);
    const uint32_t Bbase = smem_u32(B_s);
    const int mrow = w * 16;
    const int rgrp = lane >> 2;
    const int cpos = (lane & 3) * 2;
    const uint32_t aAddr = Abase
        + (uint32_t)((mrow + (lane & 7) + (((lane >> 3) & 1) << 3)) * (BKS * 2))
        + (uint32_t)(((lane >> 4) << 3) * 2);
    const uint32_t bAddr = Bbase
        + (uint32_t)(((lane & 7) + ((lane >> 4) << 3)) * (BKS * 2))
        + (uint32_t)(((lane >> 3) & 1) << 4);

    const float bo0 = bo[0], bo1 = bo[1], bo2 = bo[2];

    unsigned tile = sNext[0];
    while (tile < N_TILES_G) {
        int b  = (int)(tile >> 9);
        int n0 = (int)(tile & 511) * 32;

        // h0 = relu(centered @ W0[:3] + gW0) -> A_s bf16
        {
            int r = t & 127, half = t >> 7;
            int p = r >> 2, q = r & 3;
            int n = n0 + p;
            int m = n + q - 2;
            m = m < 0 ? 0 : (m > NN - 1 ? NN - 1 : m);
            const float* pc = pcl_cur   + ((size_t)b * NN + m) * 3;
            const float* pn = pcl_noisy + ((size_t)b * NN + n) * 3;
            float c0 = pc[0] - pn[0], c1 = pc[1] - pn[1], c2 = pc[2] - pn[2];
            const float* gw = g_gW0 + ((size_t)b * NN + n) * 128;
#pragma unroll 8
            for (int j = half * 64; j < half * 64 + 64; j += 2) {
                float2 g2 = *(const float2*)(gw + j);
                float v0 = fmaf(c0, shW0[j],     fmaf(c1, shW0[128 + j],     fmaf(c2, shW0[256 + j],     g2.x)));
                float v1 = fmaf(c0, shW0[j + 1], fmaf(c1, shW0[128 + j + 1], fmaf(c2, shW0[256 + j + 1], g2.y)));
                *(__nv_bfloat162*)(A_s + r * (BKS * 2) + j * 2) =
                    __floats2bfloat162_rn(fmaxf(v0, 0.f), fmaxf(v1, 0.f));
            }
        }
        __syncthreads();

        // fp32 h fragment copy
        float h[16][4];
#pragma unroll
        for (int j = 0; j < 16; ++j) {
            int c = j * 8 + cpos;
            float2 p0 = __bfloat1622float2(*(__nv_bfloat162*)(A_s + (mrow + rgrp) * (BKS * 2) + c * 2));
            float2 p1 = __bfloat1622float2(*(__nv_bfloat162*)(A_s + (mrow + rgrp + 8) * (BKS * 2) + c * 2));
            h[j][0] = p0.x; h[j][1] = p0.y; h[j][2] = p1.x; h[j][3] = p1.y;
        }

        float acc[16][4];

        // residual block 0
        warp_gemm(aAddr, bAddr, acc);
        __syncthreads();
#pragma unroll
        for (int j = 0; j < 16; ++j) {
            int c = j * 8 + cpos;
            float b0v = shBB[c], b1v = shBB[c + 1];
            h[j][0] += fmaxf(acc[j][0] + b0v, 0.f);
            h[j][1] += fmaxf(acc[j][1] + b1v, 0.f);
            h[j][2] += fmaxf(acc[j][2] + b0v, 0.f);
            h[j][3] += fmaxf(acc[j][3] + b1v, 0.f);
            *(__nv_bfloat162*)(A_s + (mrow + rgrp) * (BKS * 2) + c * 2) =
                __floats2bfloat162_rn(h[j][0], h[j][1]);
            *(__nv_bfloat162*)(A_s + (mrow + rgrp + 8) * (BKS * 2) + c * 2) =
                __floats2bfloat162_rn(h[j][2], h[j][3]);
        }
        __syncthreads();

        // residual block 1 (regs only) + next-tile fetch behind the same barrier
        warp_gemm(aAddr, bAddr + (uint32_t)(128 * BKS * 2), acc);
        if (t == 0) sNext[0] = atomicAdd(&g_ctr[step], 1u);
        __syncthreads();
#pragma unroll
        for (int j = 0; j < 16; ++j) {
            int c = j * 8 + cpos;
            float b0v = shBB[128 + c], b1v = shBB[128 + c + 1];
            h[j][0] += fmaxf(acc[j][0] + b0v, 0.f);
            h[j][1] += fmaxf(acc[j][1] + b1v, 0.f);
            h[j][2] += fmaxf(acc[j][2] + b0v, 0.f);
            h[j][3] += fmaxf(acc[j][3] + b1v, 0.f);
        }

        // grad = h @ Wo + bo, reduce over 4 lanes
        {
            float g0[3] = {0.f, 0.f, 0.f}, g1[3] = {0.f, 0.f, 0.f};
#pragma unroll
            for (int j = 0; j < 16; ++j) {
                int c = j * 8 + cpos;
#pragma unroll
                for (int d = 0; d < 3; ++d) {
                    float w0v = shWo[c * 3 + d], w1v = shWo[(c + 1) * 3 + d];
                    g0[d] = fmaf(h[j][0], w0v, fmaf(h[j][1], w1v, g0[d]));
                    g1[d] = fmaf(h[j][2], w0v, fmaf(h[j][3], w1v, g1[d]));
                }
            }
#pragma unroll
            for (int d = 0; d < 3; ++d) {
                g0[d] += __shfl_xor_sync(0xffffffffu, g0[d], 1);
                g0[d] += __shfl_xor_sync(0xffffffffu, g0[d], 2);
                g1[d] += __shfl_xor_sync(0xffffffffu, g1[d], 1);
                g1[d] += __shfl_xor_sync(0xffffffffu, g1[d], 2);
            }
            if ((lane & 3) == 0) {
                int r = mrow + rgrp;
                float* gp0 = g_grad + (((size_t)b * NN + n0) * 4 + r) * 3;
                float* gp1 = g_grad + (((size_t)b * NN + n0) * 4 + r + 8) * 3;
                gp0[0] = g0[0] + bo0; gp0[1] = g0[1] + bo1; gp0[2] = g0[2] + bo2;
                gp1[0] = g1[0] + bo0; gp1[1] = g1[1] + bo1; gp1[2] = g1[2] + bo2;
            }
        }

        tile = sNext[0];
    }
}

// ================= gather + update =================
__global__ void gather_kernel(float* __restrict__ pcl, float s)
{
    int idx = blockIdx.x * blockDim.x + threadIdx.x;
    if (idx >= BN * NN) return;
    int b = idx / NN, m = idx - b * NN;
    const float* G = g_grad + (size_t)b * NN * 12;

    float a0 = 0.f, a1 = 0.f, a2 = 0.f;
#pragma unroll
    for (int k = 0; k < 4; ++k) {
        int n = m + 2 - k;
        if (n >= 0 && n < NN) {
            const float* g = G + ((size_t)n * 4 + k) * 3;
            a0 += g[0]; a1 += g[1]; a2 += g[2];
        }
    }
    if (m == 0) {
        a0 += G[0] + G[3] + G[12];
        a1 += G[1] + G[4] + G[13];
        a2 += G[2] + G[5] + G[14];
    }
    if (m == NN - 1) {
        const float* g = G + (((size_t)(NN - 1)) * 4 + 3) * 3;
        a0 += g[0]; a1 += g[1]; a2 += g[2];
    }
    float* p = pcl + (size_t)idx * 3;
    p[0] += s * a0; p[1] += s * a1; p[2] += s * a2;
}

// ================= launch =================
extern "C" void kernel_launch(void* const* d_in, const int* in_sizes, int n_in,
                              void* d_out, int out_size)
{
    const float* pcl = (const float*)d_in[0];
    const float* Wf1 = (const float*)d_in[1];
    const float* bf1 = (const float*)d_in[2];
    const float* Wf2 = (const float*)d_in[3];
    const float* bf2 = (const float*)d_in[4];
    const float* W0  = (const float*)d_in[5];
    const float* b0  = (const float*)d_in[6];
    const float* Wb  = (const float*)d_in[7];
    const float* bb  = (const float*)d_in[8];
    const float* Wo  = (const float*)d_in[9];
    const float* bo  = (const float*)d_in[10];
    float* out = (float*)d_out;

    cudaFuncSetAttribute(precompute_mma, cudaFuncAttributeMaxDynamicSharedMemorySize, GK_SMEM);
    cudaFuncSetAttribute(grad_kernel_mma, cudaFuncAttributeMaxDynamicSharedMemorySize, GK_SMEM);

    convert_w_kernel<<<(4 * 128 * 128 + 255) / 256, 256>>>(Wb, Wf2, W0);
    precompute_mma<<<GRID_P, 256, GK_SMEM>>>(pcl, Wf1, bf1, bf2, b0, out);

    float s = 0.2f;
    for (int step = 0; step < 4; ++step) {
        grad_kernel_mma<<<GRID_P, 256, GK_SMEM>>>(pcl, out, W0, bb, Wo, bo, step);
        gather_kernel<<<(BN * NN + 255) / 256, 256>>>(out, s);
        s *= 0.95f;
    }
}

// round 8
// speedup vs baseline: 1.1739x; 1.1739x over previous
#include <cuda_runtime.h>
#include <cuda_bf16.h>
#include <cstdint>

// ---------------- problem constants ----------------
#define BN 2
#define NN 16384
#define BKS 136           // bf16 B row stride (elements): 272 B, conflict-free ldmatrix
#define GRID_G 296        // grad persistent grid: 148 SMs x 2 CTAs
#define N_STRIPS_G (BN * NN * 4 / 16)   // 8192 warp strips (4 points x 4 nbrs = 16 rows)
#define N_STRIPS_P (BN * NN / 16)       // 2048 precompute strips (16 points)

// ---------------- device scratch ----------------
__device__ __align__(256) float g_gW0[BN * NN * 128];              // feat @ W0[3:] + b0
__device__ __align__(256) float g_grad[BN * NN * 4 * 3];           // per-(n,k) grad_pred
__device__ __align__(256) __nv_bfloat16 g_Wb[2 * 128 * BKS];       // Wb^T bf16, padded
__device__ __align__(256) __nv_bfloat16 g_Wf2T[128 * BKS];         // Wf2^T bf16
__device__ __align__(256) __nv_bfloat16 g_W03T[128 * BKS];         // (W0[3:])^T bf16
__device__ unsigned g_ctr[4];                                      // per-step strip counters

// ================= helpers =================
__device__ __forceinline__ uint32_t smem_u32(const void* p) {
    uint32_t a;
    asm("{ .reg .u64 t; cvta.to.shared.u64 t, %1; cvt.u32.u64 %0, t; }" : "=r"(a) : "l"(p));
    return a;
}
__device__ __forceinline__ void ldsm4(uint32_t r[4], uint32_t addr) {
    asm volatile("ldmatrix.sync.aligned.m8n8.x4.shared.b16 {%0,%1,%2,%3}, [%4];"
                 : "=r"(r[0]), "=r"(r[1]), "=r"(r[2]), "=r"(r[3]) : "r"(addr));
}
__device__ __forceinline__ void mma_bf16(float d[4], uint32_t a0, uint32_t a1,
                                         uint32_t a2, uint32_t a3,
                                         uint32_t b0, uint32_t b1) {
    asm volatile(
        "mma.sync.aligned.m16n8k16.row.col.f32.bf16.bf16.f32 "
        "{%0,%1,%2,%3}, {%4,%5,%6,%7}, {%8,%9}, {%0,%1,%2,%3};"
        : "+f"(d[0]), "+f"(d[1]), "+f"(d[2]), "+f"(d[3])
        : "r"(a0), "r"(a1), "r"(a2), "r"(a3), "r"(b0), "r"(b1));
}
__device__ __forceinline__ uint32_t packbf(float a, float b) {
    __nv_bfloat162 t = __floats2bfloat162_rn(a, b);
    return *(uint32_t*)&t;
}
__device__ __forceinline__ float2 unpackbf(uint32_t u) {
    return __bfloat1622float2(*(__nv_bfloat162*)&u);
}

// one n-half (64 cols) of a 16x128x128 warp GEMM; A = hA fragments in regs
__device__ __forceinline__ void gemm_half(const uint32_t hA[16][2], uint32_t bHalf,
                                          float acc[8][4]) {
#pragma unroll
    for (int a = 0; a < 8; ++a)
#pragma unroll
        for (int i = 0; i < 4; ++i) acc[a][i] = 0.f;
#pragma unroll
    for (int s = 0; s < 8; ++s) {
        uint32_t a0 = hA[2 * s][0], a1 = hA[2 * s][1];
        uint32_t a2 = hA[2 * s + 1][0], a3 = hA[2 * s + 1][1];
#pragma unroll
        for (int jj = 0; jj < 4; ++jj) {
            uint32_t bf[4];
            ldsm4(bf, bHalf + (uint32_t)(jj * 16 * (BKS * 2)) + s * 32);
            mma_bf16(acc[2 * jj],     a0, a1, a2, a3, bf[0], bf[1]);
            mma_bf16(acc[2 * jj + 1], a0, a1, a2, a3, bf[2], bf[3]);
        }
    }
}

// ================= convert: weights -> bf16 transposed/padded; reset counters =================
__global__ void convert_w_kernel(const float* __restrict__ Wb,
                                 const float* __restrict__ Wf2,
                                 const float* __restrict__ W0)
{
    int idx = blockIdx.x * blockDim.x + threadIdx.x;
    if (idx < 4) g_ctr[idx] = 0;
    if (idx >= 4 * 128 * 128) return;
    int seg = idx >> 14;
    int rem = idx & 16383;
    int n = rem >> 7, k = rem & 127;
    if (seg < 2) {
        g_Wb[seg * 128 * BKS + n * BKS + k] = __float2bfloat16(Wb[seg * 16384 + k * 128 + n]);
    } else if (seg == 2) {
        g_Wf2T[n * BKS + k] = __float2bfloat16(Wf2[k * 128 + n]);
    } else {
        g_W03T[n * BKS + k] = __float2bfloat16(W0[(3 + k) * 128 + n]);
    }
}

// ================= SMEM layouts =================
#define BMAT_BYTES (128 * BKS * 2)          // 34816 per weight matrix
#define GK_SMEM  (2 * BMAT_BYTES + 4096)    // grad: Wb0,Wb1 + W0/Wo/bb        = 73728
#define PK_SMEM  (2 * BMAT_BYTES + 3072)    // pre:  Wf2T,W03T + Wf1/bf1/bf2/b0 = 72704

// ================= precompute: warp-autonomous, one 16-point strip per warp =================
__global__ __launch_bounds__(256, 2)
void precompute_mma(const float* __restrict__ pcl,
                    const float* __restrict__ Wf1, const float* __restrict__ bf1,
                    const float* __restrict__ bf2, const float* __restrict__ b0,
                    float* __restrict__ out)
{
    extern __shared__ __align__(256) char smc[];
    const int t    = threadIdx.x;
    const int lane = t & 31;
    const int w    = t >> 5;

    char* B_s = smc;
    float* shWf1 = (float*)(smc + 2 * BMAT_BYTES);
    float* shbf1 = shWf1 + 384;
    float* shbf2 = shbf1 + 128;
    float* shb0  = shbf2 + 128;

    for (int i = t; i < 384; i += 256) shWf1[i] = Wf1[i];
    if (t < 128) { shbf1[t] = bf1[t]; shbf2[t] = bf2[t]; shb0[t] = b0[t]; }
    {
        const uint4* s1 = (const uint4*)g_Wf2T;
        const uint4* s2 = (const uint4*)g_W03T;
        uint4* d1 = (uint4*)B_s;
        uint4* d2 = (uint4*)(B_s + BMAT_BYTES);
        for (int i = t; i < BMAT_BYTES / 16; i += 256) { d1[i] = s1[i]; d2[i] = s2[i]; }
    }
    __syncthreads();

    const int sp = blockIdx.x * 8 + w;      // one strip per warp
    if (sp >= N_STRIPS_P) return;
    const int b  = sp >> 10;                // 1024 strips per batch
    const int p0 = (sp & 1023) * 16;

    const int rgrp = lane >> 2;
    const int cpos = (lane & 3) * 2;
    const uint32_t Bbase = smem_u32(B_s);
    const uint32_t bAddr = Bbase
        + (uint32_t)(((lane & 7) + ((lane >> 4) << 3)) * (BKS * 2))
        + (uint32_t)(((lane >> 3) & 1) << 4);

    const float* pclb = pcl + ((size_t)b * NN + p0) * 3;
    float* outb = out + ((size_t)b * NN + p0) * 3;
    for (int i = lane; i < 48; i += 32) outb[i] = pclb[i];

    // rows this thread owns: rgrp and rgrp+8 (points p0+rgrp, p0+rgrp+8)
    float xl0 = pclb[rgrp * 3 + 0], xl1 = pclb[rgrp * 3 + 1], xl2 = pclb[rgrp * 3 + 2];
    float xh0 = pclb[(rgrp + 8) * 3 + 0], xh1 = pclb[(rgrp + 8) * 3 + 1], xh2 = pclb[(rgrp + 8) * 3 + 2];

    // h1 = relu(pcl @ Wf1 + bf1) directly in fragment layout
    uint32_t hA[16][2];
#pragma unroll
    for (int j = 0; j < 16; ++j) {
        int c = j * 8 + cpos;
        float w0a = shWf1[c],       w1a = shWf1[128 + c],       w2a = shWf1[256 + c],       ba = shbf1[c];
        float w0b = shWf1[c + 1],   w1b = shWf1[128 + c + 1],   w2b = shWf1[256 + c + 1],   bbv = shbf1[c + 1];
        float vl0 = fmaf(xl0, w0a, fmaf(xl1, w1a, fmaf(xl2, w2a, ba)));
        float vl1 = fmaf(xl0, w0b, fmaf(xl1, w1b, fmaf(xl2, w2b, bbv)));
        float vh0 = fmaf(xh0, w0a, fmaf(xh1, w1a, fmaf(xh2, w2a, ba)));
        float vh1 = fmaf(xh0, w0b, fmaf(xh1, w1b, fmaf(xh2, w2b, bbv)));
        hA[j][0] = packbf(fmaxf(vl0, 0.f), fmaxf(vl1, 0.f));
        hA[j][1] = packbf(fmaxf(vh0, 0.f), fmaxf(vh1, 0.f));
    }

    // GEMM1: feat = h1 @ Wf2 + bf2 (no relu) -> hA
    {
        uint32_t hN[16][2];
#pragma unroll
        for (int half = 0; half < 2; ++half) {
            float acc[8][4];
            gemm_half(hA, bAddr + (uint32_t)(half * 64 * (BKS * 2)), acc);
#pragma unroll
            for (int a = 0; a < 8; ++a) {
                int j = half * 8 + a;
                int c = j * 8 + cpos;
                float b0v = shbf2[c], b1v = shbf2[c + 1];
                hN[j][0] = packbf(acc[a][0] + b0v, acc[a][1] + b1v);
                hN[j][1] = packbf(acc[a][2] + b0v, acc[a][3] + b1v);
            }
        }
#pragma unroll
        for (int j = 0; j < 16; ++j) { hA[j][0] = hN[j][0]; hA[j][1] = hN[j][1]; }
    }

    // GEMM2: gW0 = feat @ W0[3:] + b0 -> global fp32
    {
        float* gb = g_gW0 + ((size_t)b * NN + p0) * 128;
#pragma unroll
        for (int half = 0; half < 2; ++half) {
            float acc[8][4];
            gemm_half(hA, bAddr + (uint32_t)BMAT_BYTES + (uint32_t)(half * 64 * (BKS * 2)), acc);
#pragma unroll
            for (int a = 0; a < 8; ++a) {
                int j = half * 8 + a;
                int c = j * 8 + cpos;
                float b0v = shb0[c], b1v = shb0[c + 1];
                *(float2*)(gb + (size_t)rgrp * 128 + c)       = make_float2(acc[a][0] + b0v, acc[a][1] + b1v);
                *(float2*)(gb + (size_t)(rgrp + 8) * 128 + c) = make_float2(acc[a][2] + b0v, acc[a][3] + b1v);
            }
        }
    }
}

// ================= grad kernel: warp-autonomous, dynamic per-warp strips =================
__global__ __launch_bounds__(256, 2)
void grad_kernel_mma(const float* __restrict__ pcl_noisy, const float* __restrict__ pcl_cur,
                     const float* __restrict__ W0, const float* __restrict__ bb,
                     const float* __restrict__ Wo, const float* __restrict__ bo,
                     int step)
{
    extern __shared__ __align__(256) char smc[];
    const int t    = threadIdx.x;
    const int lane = t & 31;

    char* B_s = smc;
    float* shW0 = (float*)(smc + 2 * BMAT_BYTES);
    float* shWo = shW0 + 384;
    float* shBB = shWo + 384;

    for (int i = t; i < 384; i += 256) { shW0[i] = W0[i]; shWo[i] = Wo[i]; }
    if (t < 256) shBB[t] = bb[t];
    {
        const uint4* src = (const uint4*)g_Wb;
        uint4* dst = (uint4*)B_s;
        for (int i = t; i < 2 * BMAT_BYTES / 16; i += 256) dst[i] = src[i];
    }
    __syncthreads();   // only barrier in the kernel

    const int rgrp = lane >> 2;
    const int cpos = (lane & 3) * 2;
    const uint32_t Bbase = smem_u32(B_s);
    const uint32_t bAddr = Bbase
        + (uint32_t)(((lane & 7) + ((lane >> 4) << 3)) * (BKS * 2))
        + (uint32_t)(((lane >> 3) & 1) << 4);

    const float bo0 = bo[0], bo1 = bo[1], bo2 = bo[2];

    unsigned nxt = 0, strip;
    if (lane == 0) nxt = atomicAdd(&g_ctr[step], 1u);
    strip = __shfl_sync(0xffffffffu, nxt, 0);

    while (strip < N_STRIPS_G) {
        if (lane == 0) nxt = atomicAdd(&g_ctr[step], 1u);   // prefetch next strip id

        const int b  = (int)(strip >> 12);                  // 4096 strips per batch
        const int p0 = (int)(strip & 4095) * 4;

        // rows rgrp and rgrp+8 of this 16-row strip
        int r_lo = rgrp, r_hi = rgrp + 8;
        int n_lo = p0 + (r_lo >> 2), q_lo = r_lo & 3;
        int n_hi = p0 + (r_hi >> 2), q_hi = r_hi & 3;
        int m_lo = n_lo + q_lo - 2; m_lo = m_lo < 0 ? 0 : (m_lo > NN - 1 ? NN - 1 : m_lo);
        int m_hi = n_hi + q_hi - 2; m_hi = m_hi < 0 ? 0 : (m_hi > NN - 1 ? NN - 1 : m_hi);

        const float* pcl_b = pcl_cur   + (size_t)b * NN * 3;
        const float* pn_b  = pcl_noisy + (size_t)b * NN * 3;
        float cl0 = pcl_b[m_lo * 3 + 0] - pn_b[n_lo * 3 + 0];
        float cl1 = pcl_b[m_lo * 3 + 1] - pn_b[n_lo * 3 + 1];
        float cl2 = pcl_b[m_lo * 3 + 2] - pn_b[n_lo * 3 + 2];
        float ch0 = pcl_b[m_hi * 3 + 0] - pn_b[n_hi * 3 + 0];
        float ch1 = pcl_b[m_hi * 3 + 1] - pn_b[n_hi * 3 + 1];
        float ch2 = pcl_b[m_hi * 3 + 2] - pn_b[n_hi * 3 + 2];

        const float* gwl = g_gW0 + ((size_t)b * NN + n_lo) * 128;
        const float* gwh = g_gW0 + ((size_t)b * NN + n_hi) * 128;

        // h0 = relu(centered @ W0[:3] + gW0) directly in fragment layout
        uint32_t hA[16][2];
#pragma unroll
        for (int j = 0; j < 16; ++j) {
            int c = j * 8 + cpos;
            float2 gl = *(const float2*)(gwl + c);
            float2 gh = *(const float2*)(gwh + c);
            float w0a = shW0[c],     w1a = shW0[128 + c],     w2a = shW0[256 + c];
            float w0b = shW0[c + 1], w1b = shW0[128 + c + 1], w2b = shW0[256 + c + 1];
            float vl0 = fmaf(cl0, w0a, fmaf(cl1, w1a, fmaf(cl2, w2a, gl.x)));
            float vl1 = fmaf(cl0, w0b, fmaf(cl1, w1b, fmaf(cl2, w2b, gl.y)));
            float vh0 = fmaf(ch0, w0a, fmaf(ch1, w1a, fmaf(ch2, w2a, gh.x)));
            float vh1 = fmaf(ch0, w0b, fmaf(ch1, w1b, fmaf(ch2, w2b, gh.y)));
            hA[j][0] = packbf(fmaxf(vl0, 0.f), fmaxf(vl1, 0.f));
            hA[j][1] = packbf(fmaxf(vh0, 0.f), fmaxf(vh1, 0.f));
        }

        // two residual blocks, all in registers
#pragma unroll
        for (int blk = 0; blk < 2; ++blk) {
            uint32_t bBlk = bAddr + (uint32_t)(blk * BMAT_BYTES);
            uint32_t hN[16][2];
#pragma unroll
            for (int half = 0; half < 2; ++half) {
                float acc[8][4];
                gemm_half(hA, bBlk + (uint32_t)(half * 64 * (BKS * 2)), acc);
#pragma unroll
                for (int a = 0; a < 8; ++a) {
                    int j = half * 8 + a;
                    int c = j * 8 + cpos;
                    float b0v = shBB[blk * 128 + c], b1v = shBB[blk * 128 + c + 1];
                    float2 lo = unpackbf(hA[j][0]);
                    float2 hi = unpackbf(hA[j][1]);
                    lo.x += fmaxf(acc[a][0] + b0v, 0.f);
                    lo.y += fmaxf(acc[a][1] + b1v, 0.f);
                    hi.x += fmaxf(acc[a][2] + b0v, 0.f);
                    hi.y += fmaxf(acc[a][3] + b1v, 0.f);
                    hN[j][0] = packbf(lo.x, lo.y);
                    hN[j][1] = packbf(hi.x, hi.y);
                }
            }
#pragma unroll
            for (int j = 0; j < 16; ++j) { hA[j][0] = hN[j][0]; hA[j][1] = hN[j][1]; }
        }

        // grad = h @ Wo + bo, reduce over 4 lanes per row pair
        {
            float g0[3] = {0.f, 0.f, 0.f}, g1[3] = {0.f, 0.f, 0.f};
#pragma unroll
            for (int j = 0; j < 16; ++j) {
                int c = j * 8 + cpos;
                float2 lo = unpackbf(hA[j][0]);
                float2 hi = unpackbf(hA[j][1]);
#pragma unroll
                for (int d = 0; d < 3; ++d) {
                    float w0v = shWo[c * 3 + d], w1v = shWo[(c + 1) * 3 + d];
                    g0[d] = fmaf(lo.x, w0v, fmaf(lo.y, w1v, g0[d]));
                    g1[d] = fmaf(hi.x, w0v, fmaf(hi.y, w1v, g1[d]));
                }
            }
#pragma unroll
            for (int d = 0; d < 3; ++d) {
                g0[d] += __shfl_xor_sync(0xffffffffu, g0[d], 1);
                g0[d] += __shfl_xor_sync(0xffffffffu, g0[d], 2);
                g1[d] += __shfl_xor_sync(0xffffffffu, g1[d], 1);
                g1[d] += __shfl_xor_sync(0xffffffffu, g1[d], 2);
            }
            if ((lane & 3) == 0) {
                // flattened row index = (b*NN + p0)*4 + r
                float* gp0 = g_grad + (((size_t)b * NN + p0) * 4 + r_lo) * 3;
                float* gp1 = g_grad + (((size_t)b * NN + p0) * 4 + r_hi) * 3;
                gp0[0] = g0[0] + bo0; gp0[1] = g0[1] + bo1; gp0[2] = g0[2] + bo2;
                gp1[0] = g1[0] + bo0; gp1[1] = g1[1] + bo1; gp1[2] = g1[2] + bo2;
            }
        }

        strip = __shfl_sync(0xffffffffu, nxt, 0);
    }
}

// ================= gather + update =================
__global__ void gather_kernel(float* __restrict__ pcl, float s)
{
    int idx = blockIdx.x * blockDim.x + threadIdx.x;
    if (idx >= BN * NN) return;
    int b = idx / NN, m = idx - b * NN;
    const float* G = g_grad + (size_t)b * NN * 12;

    float a0 = 0.f, a1 = 0.f, a2 = 0.f;
#pragma unroll
    for (int k = 0; k < 4; ++k) {
        int n = m + 2 - k;
        if (n >= 0 && n < NN) {
            const float* g = G + ((size_t)n * 4 + k) * 3;
            a0 += g[0]; a1 += g[1]; a2 += g[2];
        }
    }
    if (m == 0) {
        a0 += G[0] + G[3] + G[12];
        a1 += G[1] + G[4] + G[13];
        a2 += G[2] + G[5] + G[14];
    }
    if (m == NN - 1) {
        const float* g = G + (((size_t)(NN - 1)) * 4 + 3) * 3;
        a0 += g[0]; a1 += g[1]; a2 += g[2];
    }
    float* p = pcl + (size_t)idx * 3;
    p[0] += s * a0; p[1] += s * a1; p[2] += s * a2;
}

// ================= launch =================
extern "C" void kernel_launch(void* const* d_in, const int* in_sizes, int n_in,
                              void* d_out, int out_size)
{
    const float* pcl = (const float*)d_in[0];
    const float* Wf1 = (const float*)d_in[1];
    const float* bf1 = (const float*)d_in[2];
    const float* Wf2 = (const float*)d_in[3];
    const float* bf2 = (const float*)d_in[4];
    const float* W0  = (const float*)d_in[5];
    const float* b0  = (const float*)d_in[6];
    const float* Wb  = (const float*)d_in[7];
    const float* bb  = (const float*)d_in[8];
    const float* Wo  = (const float*)d_in[9];
    const float* bo  = (const float*)d_in[10];
    float* out = (float*)d_out;

    cudaFuncSetAttribute(precompute_mma, cudaFuncAttributeMaxDynamicSharedMemorySize, PK_SMEM);
    cudaFuncSetAttribute(grad_kernel_mma, cudaFuncAttributeMaxDynamicSharedMemorySize, GK_SMEM);

    convert_w_kernel<<<(4 * 128 * 128 + 255) / 256, 256>>>(Wb, Wf2, W0);
    precompute_mma<<<N_STRIPS_P / 8, 256, PK_SMEM>>>(pcl, Wf1, bf1, bf2, b0, out);

    float s = 0.2f;
    for (int step = 0; step < 4; ++step) {
        grad_kernel_mma<<<GRID_G, 256, GK_SMEM>>>(pcl, out, W0, bb, Wo, bo, step);
        gather_kernel<<<(BN * NN + 255) / 256, 256>>>(out, s);
        s *= 0.95f;
    }
}

// round 9
// speedup vs baseline: 1.2088x; 1.0298x over previous
#include <cuda_runtime.h>
#include <cuda_bf16.h>
#include <cstdint>

// ---------------- problem constants ----------------
#define BN 2
#define NN 16384
#define BKS 136           // bf16 B row stride (elements): 272 B, conflict-free ldmatrix
#define GRID 296          // 148 SMs x 2 CTAs — all co-resident (required for grid barrier)
#define THREADS 256
#define N_STRIPS_G (BN * NN * 4 / 16)   // 8192 grad warp strips
#define N_STRIPS_P (BN * NN / 16)       // 2048 precompute warp strips

// ---------------- device scratch ----------------
__device__ __align__(256) float g_gW0[BN * NN * 128];
__device__ __align__(256) float g_grad[BN * NN * 4 * 3];
__device__ __align__(256) __nv_bfloat16 g_Wb[2 * 128 * BKS];
__device__ __align__(256) __nv_bfloat16 g_Wf2T[128 * BKS];
__device__ __align__(256) __nv_bfloat16 g_W03T[128 * BKS];
__device__ unsigned g_ctr[4];          // per-step dynamic strip counters
__device__ unsigned g_barcnt;          // grid barrier arrive count (self-resetting)
__device__ unsigned g_bargen;          // grid barrier generation (monotonic)

// ================= helpers =================
__device__ __forceinline__ uint32_t smem_u32(const void* p) {
    uint32_t a;
    asm("{ .reg .u64 t; cvta.to.shared.u64 t, %1; cvt.u32.u64 %0, t; }" : "=r"(a) : "l"(p));
    return a;
}
__device__ __forceinline__ void ldsm4(uint32_t r[4], uint32_t addr) {
    asm volatile("ldmatrix.sync.aligned.m8n8.x4.shared.b16 {%0,%1,%2,%3}, [%4];"
                 : "=r"(r[0]), "=r"(r[1]), "=r"(r[2]), "=r"(r[3]) : "r"(addr));
}
__device__ __forceinline__ void mma_bf16(float d[4], uint32_t a0, uint32_t a1,
                                         uint32_t a2, uint32_t a3,
                                         uint32_t b0, uint32_t b1) {
    asm volatile(
        "mma.sync.aligned.m16n8k16.row.col.f32.bf16.bf16.f32 "
        "{%0,%1,%2,%3}, {%4,%5,%6,%7}, {%8,%9}, {%0,%1,%2,%3};"
        : "+f"(d[0]), "+f"(d[1]), "+f"(d[2]), "+f"(d[3])
        : "r"(a0), "r"(a1), "r"(a2), "r"(a3), "r"(b0), "r"(b1));
}
__device__ __forceinline__ uint32_t packbf(float a, float b) {
    __nv_bfloat162 t = __floats2bfloat162_rn(a, b);
    return *(uint32_t*)&t;
}
__device__ __forceinline__ float2 unpackbf(uint32_t u) {
    return __bfloat1622float2(*(__nv_bfloat162*)&u);
}

// sense-reversing software grid barrier (all GRID CTAs must be resident)
__device__ __forceinline__ void grid_bar() {
    __syncthreads();
    if (threadIdx.x == 0) {
        __threadfence();
        unsigned gen;
        asm volatile("ld.volatile.global.u32 %0, [%1];" : "=r"(gen) : "l"(&g_bargen));
        unsigned a = atomicAdd(&g_barcnt, 1u);
        if (a == GRID - 1u) {
            asm volatile("st.volatile.global.u32 [%0], %1;" :: "l"(&g_barcnt), "r"(0u) : "memory");
            __threadfence();
            atomicAdd(&g_bargen, 1u);
        } else {
            unsigned cur;
            do {
                asm volatile("ld.volatile.global.u32 %0, [%1];" : "=r"(cur) : "l"(&g_bargen));
            } while (cur == gen);
        }
        __threadfence();
    }
    __syncthreads();
}

// one n-half (64 cols) of a 16x128x128 warp GEMM; A fragments in regs
__device__ __forceinline__ void gemm_half(const uint32_t hA[16][2], uint32_t bHalf,
                                          float acc[8][4]) {
#pragma unroll
    for (int a = 0; a < 8; ++a)
#pragma unroll
        for (int i = 0; i < 4; ++i) acc[a][i] = 0.f;
#pragma unroll
    for (int s = 0; s < 8; ++s) {
        uint32_t a0 = hA[2 * s][0], a1 = hA[2 * s][1];
        uint32_t a2 = hA[2 * s + 1][0], a3 = hA[2 * s + 1][1];
#pragma unroll
        for (int jj = 0; jj < 4; ++jj) {
            uint32_t bf[4];
            ldsm4(bf, bHalf + (uint32_t)(jj * 16 * (BKS * 2)) + s * 32);
            mma_bf16(acc[2 * jj],     a0, a1, a2, a3, bf[0], bf[1]);
            mma_bf16(acc[2 * jj + 1], a0, a1, a2, a3, bf[2], bf[3]);
        }
    }
}

// ================= SMEM =================
#define BMAT_BYTES (128 * BKS * 2)                 // 34816
#define MISC_FLOATS 1792
#define SMEM_TOTAL (2 * BMAT_BYTES + MISC_FLOATS * 4 + 512)   // 77824 -> 2 CTAs/SM

// ================= the fused persistent kernel =================
__global__ __launch_bounds__(THREADS, 2)
void fused_denoise(const float* __restrict__ pcl,
                   const float* __restrict__ Wf1, const float* __restrict__ bf1,
                   const float* __restrict__ Wf2, const float* __restrict__ bf2,
                   const float* __restrict__ W0,  const float* __restrict__ b0,
                   const float* __restrict__ Wb,  const float* __restrict__ bb,
                   const float* __restrict__ Wo,  const float* __restrict__ bo,
                   float* __restrict__ out)
{
    extern __shared__ __align__(256) char smc[];
    const int t    = threadIdx.x;
    const int lane = t & 31;
    const int w    = t >> 5;
    const int gtid = blockIdx.x * THREADS + t;

    char* B_s = smc;
    float* shW0  = (float*)(smc + 2 * BMAT_BYTES);
    float* shWo  = shW0 + 384;
    float* shBB  = shWo + 384;
    float* shWf1 = shBB + 256;
    float* shbf1 = shWf1 + 384;
    float* shbf2 = shbf1 + 128;
    float* shb0  = shbf2 + 128;

    // ---------- phase 0: convert weights to bf16 transposed/padded; reset counters ----------
    for (int idx = gtid; idx < 4 * 128 * 128; idx += GRID * THREADS) {
        int seg = idx >> 14;
        int rem = idx & 16383;
        int n = rem >> 7, k = rem & 127;
        if (seg < 2) {
            g_Wb[seg * 128 * BKS + n * BKS + k] = __float2bfloat16(Wb[seg * 16384 + k * 128 + n]);
        } else if (seg == 2) {
            g_Wf2T[n * BKS + k] = __float2bfloat16(Wf2[k * 128 + n]);
        } else {
            g_W03T[n * BKS + k] = __float2bfloat16(W0[(3 + k) * 128 + n]);
        }
    }
    if (blockIdx.x == 0 && t < 4) g_ctr[t] = 0;
    grid_bar();

    // ---------- stage all misc weights + precompute B matrices ----------
    for (int i = t; i < 384; i += THREADS) {
        shW0[i] = W0[i]; shWo[i] = Wo[i]; shWf1[i] = Wf1[i];
    }
    if (t < 256) shBB[t] = bb[t];
    if (t < 128) { shbf1[t] = bf1[t]; shbf2[t] = bf2[t]; shb0[t] = b0[t]; }
    {
        const uint4* s1 = (const uint4*)g_Wf2T;
        const uint4* s2 = (const uint4*)g_W03T;
        uint4* d1 = (uint4*)B_s;
        uint4* d2 = (uint4*)(B_s + BMAT_BYTES);
        for (int i = t; i < BMAT_BYTES / 16; i += THREADS) { d1[i] = s1[i]; d2[i] = s2[i]; }
    }
    __syncthreads();

    const int rgrp = lane >> 2;
    const int cpos = (lane & 3) * 2;
    const uint32_t Bbase = smem_u32(B_s);
    const uint32_t bAddr = Bbase
        + (uint32_t)(((lane & 7) + ((lane >> 4) << 3)) * (BKS * 2))
        + (uint32_t)(((lane >> 3) & 1) << 4);

    // ---------- phase 1: precompute (one 16-point strip per warp, static) ----------
    {
        const int sp = blockIdx.x * 8 + w;
        if (sp < N_STRIPS_P) {
            const int b  = sp >> 10;
            const int p0 = (sp & 1023) * 16;
            const float* pclb = pcl + ((size_t)b * NN + p0) * 3;
            float* outb = out + ((size_t)b * NN + p0) * 3;
            for (int i = lane; i < 48; i += 32) outb[i] = pclb[i];

            float xl0 = pclb[rgrp * 3 + 0], xl1 = pclb[rgrp * 3 + 1], xl2 = pclb[rgrp * 3 + 2];
            float xh0 = pclb[(rgrp + 8) * 3 + 0], xh1 = pclb[(rgrp + 8) * 3 + 1], xh2 = pclb[(rgrp + 8) * 3 + 2];

            uint32_t hA[16][2];
#pragma unroll
            for (int j = 0; j < 16; ++j) {
                int c = j * 8 + cpos;
                float w0a = shWf1[c],     w1a = shWf1[128 + c],     w2a = shWf1[256 + c],     ba  = shbf1[c];
                float w0b = shWf1[c + 1], w1b = shWf1[128 + c + 1], w2b = shWf1[256 + c + 1], bbv = shbf1[c + 1];
                float vl0 = fmaf(xl0, w0a, fmaf(xl1, w1a, fmaf(xl2, w2a, ba)));
                float vl1 = fmaf(xl0, w0b, fmaf(xl1, w1b, fmaf(xl2, w2b, bbv)));
                float vh0 = fmaf(xh0, w0a, fmaf(xh1, w1a, fmaf(xh2, w2a, ba)));
                float vh1 = fmaf(xh0, w0b, fmaf(xh1, w1b, fmaf(xh2, w2b, bbv)));
                hA[j][0] = packbf(fmaxf(vl0, 0.f), fmaxf(vl1, 0.f));
                hA[j][1] = packbf(fmaxf(vh0, 0.f), fmaxf(vh1, 0.f));
            }

            // GEMM1: feat = h1 @ Wf2 + bf2 (no relu)
            {
                uint32_t hN[16][2];
#pragma unroll
                for (int half = 0; half < 2; ++half) {
                    float acc[8][4];
                    gemm_half(hA, bAddr + (uint32_t)(half * 64 * (BKS * 2)), acc);
#pragma unroll
                    for (int a = 0; a < 8; ++a) {
                        int j = half * 8 + a;
                        int c = j * 8 + cpos;
                        float b0v = shbf2[c], b1v = shbf2[c + 1];
                        hN[j][0] = packbf(acc[a][0] + b0v, acc[a][1] + b1v);
                        hN[j][1] = packbf(acc[a][2] + b0v, acc[a][3] + b1v);
                    }
                }
#pragma unroll
                for (int j = 0; j < 16; ++j) { hA[j][0] = hN[j][0]; hA[j][1] = hN[j][1]; }
            }

            // GEMM2: gW0 = feat @ W0[3:] + b0
            {
                float* gb = g_gW0 + ((size_t)b * NN + p0) * 128;
#pragma unroll
                for (int half = 0; half < 2; ++half) {
                    float acc[8][4];
                    gemm_half(hA, bAddr + (uint32_t)BMAT_BYTES + (uint32_t)(half * 64 * (BKS * 2)), acc);
#pragma unroll
                    for (int a = 0; a < 8; ++a) {
                        int j = half * 8 + a;
                        int c = j * 8 + cpos;
                        float b0v = shb0[c], b1v = shb0[c + 1];
                        *(float2*)(gb + (size_t)rgrp * 128 + c)       = make_float2(acc[a][0] + b0v, acc[a][1] + b1v);
                        *(float2*)(gb + (size_t)(rgrp + 8) * 128 + c) = make_float2(acc[a][2] + b0v, acc[a][3] + b1v);
                    }
                }
            }
        }
    }
    grid_bar();

    // ---------- reload B_s with Wb0, Wb1 ----------
    {
        const uint4* src = (const uint4*)g_Wb;
        uint4* dst = (uint4*)B_s;
        for (int i = t; i < 2 * BMAT_BYTES / 16; i += THREADS) dst[i] = src[i];
    }
    __syncthreads();

    const float bo0 = bo[0], bo1 = bo[1], bo2 = bo[2];
    float s = 0.2f;

    // ---------- 4 denoise steps ----------
    for (int step = 0; step < 4; ++step) {
        // ---- grad phase: dynamic per-warp strips ----
        unsigned nxt = 0, strip;
        if (lane == 0) nxt = atomicAdd(&g_ctr[step], 1u);
        strip = __shfl_sync(0xffffffffu, nxt, 0);

        while (strip < N_STRIPS_G) {
            if (lane == 0) nxt = atomicAdd(&g_ctr[step], 1u);

            const int b  = (int)(strip >> 12);
            const int p0 = (int)(strip & 4095) * 4;

            int r_lo = rgrp, r_hi = rgrp + 8;
            int n_lo = p0 + (r_lo >> 2), q_lo = r_lo & 3;
            int n_hi = p0 + (r_hi >> 2), q_hi = r_hi & 3;
            int m_lo = n_lo + q_lo - 2; m_lo = m_lo < 0 ? 0 : (m_lo > NN - 1 ? NN - 1 : m_lo);
            int m_hi = n_hi + q_hi - 2; m_hi = m_hi < 0 ? 0 : (m_hi > NN - 1 ? NN - 1 : m_hi);

            const float* pcl_b = out       + (size_t)b * NN * 3;
            const float* pn_b  = pcl       + (size_t)b * NN * 3;
            float cl0 = pcl_b[m_lo * 3 + 0] - pn_b[n_lo * 3 + 0];
            float cl1 = pcl_b[m_lo * 3 + 1] - pn_b[n_lo * 3 + 1];
            float cl2 = pcl_b[m_lo * 3 + 2] - pn_b[n_lo * 3 + 2];
            float ch0 = pcl_b[m_hi * 3 + 0] - pn_b[n_hi * 3 + 0];
            float ch1 = pcl_b[m_hi * 3 + 1] - pn_b[n_hi * 3 + 1];
            float ch2 = pcl_b[m_hi * 3 + 2] - pn_b[n_hi * 3 + 2];

            const float* gwl = g_gW0 + ((size_t)b * NN + n_lo) * 128;
            const float* gwh = g_gW0 + ((size_t)b * NN + n_hi) * 128;

            uint32_t hA[16][2];
#pragma unroll
            for (int j = 0; j < 16; ++j) {
                int c = j * 8 + cpos;
                float2 gl = *(const float2*)(gwl + c);
                float2 gh = *(const float2*)(gwh + c);
                float w0a = shW0[c],     w1a = shW0[128 + c],     w2a = shW0[256 + c];
                float w0b = shW0[c + 1], w1b = shW0[128 + c + 1], w2b = shW0[256 + c + 1];
                float vl0 = fmaf(cl0, w0a, fmaf(cl1, w1a, fmaf(cl2, w2a, gl.x)));
                float vl1 = fmaf(cl0, w0b, fmaf(cl1, w1b, fmaf(cl2, w2b, gl.y)));
                float vh0 = fmaf(ch0, w0a, fmaf(ch1, w1a, fmaf(ch2, w2a, gh.x)));
                float vh1 = fmaf(ch0, w0b, fmaf(ch1, w1b, fmaf(ch2, w2b, gh.y)));
                hA[j][0] = packbf(fmaxf(vl0, 0.f), fmaxf(vl1, 0.f));
                hA[j][1] = packbf(fmaxf(vh0, 0.f), fmaxf(vh1, 0.f));
            }

#pragma unroll
            for (int blk = 0; blk < 2; ++blk) {
                uint32_t bBlk = bAddr + (uint32_t)(blk * BMAT_BYTES);
                uint32_t hN[16][2];
#pragma unroll
                for (int half = 0; half < 2; ++half) {
                    float acc[8][4];
                    gemm_half(hA, bBlk + (uint32_t)(half * 64 * (BKS * 2)), acc);
#pragma unroll
                    for (int a = 0; a < 8; ++a) {
                        int j = half * 8 + a;
                        int c = j * 8 + cpos;
                        float b0v = shBB[blk * 128 + c], b1v = shBB[blk * 128 + c + 1];
                        float2 lo = unpackbf(hA[j][0]);
                        float2 hi = unpackbf(hA[j][1]);
                        lo.x += fmaxf(acc[a][0] + b0v, 0.f);
                        lo.y += fmaxf(acc[a][1] + b1v, 0.f);
                        hi.x += fmaxf(acc[a][2] + b0v, 0.f);
                        hi.y += fmaxf(acc[a][3] + b1v, 0.f);
                        hN[j][0] = packbf(lo.x, lo.y);
                        hN[j][1] = packbf(hi.x, hi.y);
                    }
                }
#pragma unroll
                for (int j = 0; j < 16; ++j) { hA[j][0] = hN[j][0]; hA[j][1] = hN[j][1]; }
            }

            {
                float g0[3] = {0.f, 0.f, 0.f}, g1[3] = {0.f, 0.f, 0.f};
#pragma unroll
                for (int j = 0; j < 16; ++j) {
                    int c = j * 8 + cpos;
                    float2 lo = unpackbf(hA[j][0]);
                    float2 hi = unpackbf(hA[j][1]);
#pragma unroll
                    for (int d = 0; d < 3; ++d) {
                        float w0v = shWo[c * 3 + d], w1v = shWo[(c + 1) * 3 + d];
                        g0[d] = fmaf(lo.x, w0v, fmaf(lo.y, w1v, g0[d]));
                        g1[d] = fmaf(hi.x, w0v, fmaf(hi.y, w1v, g1[d]));
                    }
                }
#pragma unroll
                for (int d = 0; d < 3; ++d) {
                    g0[d] += __shfl_xor_sync(0xffffffffu, g0[d], 1);
                    g0[d] += __shfl_xor_sync(0xffffffffu, g0[d], 2);
                    g1[d] += __shfl_xor_sync(0xffffffffu, g1[d], 1);
                    g1[d] += __shfl_xor_sync(0xffffffffu, g1[d], 2);
                }
                if ((lane & 3) == 0) {
                    float* gp0 = g_grad + (((size_t)b * NN + p0) * 4 + r_lo) * 3;
                    float* gp1 = g_grad + (((size_t)b * NN + p0) * 4 + r_hi) * 3;
                    gp0[0] = g0[0] + bo0; gp0[1] = g0[1] + bo1; gp0[2] = g0[2] + bo2;
                    gp1[0] = g1[0] + bo0; gp1[1] = g1[1] + bo1; gp1[2] = g1[2] + bo2;
                }
            }

            strip = __shfl_sync(0xffffffffu, nxt, 0);
        }
        grid_bar();   // grads visible

        // ---- gather phase: full-grid, one point per thread ----
        for (int idx = gtid; idx < BN * NN; idx += GRID * THREADS) {
            int b = idx / NN, m = idx - b * NN;
            const float* G = g_grad + (size_t)b * NN * 12;
            float a0 = 0.f, a1 = 0.f, a2 = 0.f;
#pragma unroll
            for (int k = 0; k < 4; ++k) {
                int n = m + 2 - k;
                if (n >= 0 && n < NN) {
                    const float* g = G + ((size_t)n * 4 + k) * 3;
                    a0 += g[0]; a1 += g[1]; a2 += g[2];
                }
            }
            if (m == 0) {
                a0 += G[0] + G[3] + G[12];
                a1 += G[1] + G[4] + G[13];
                a2 += G[2] + G[5] + G[14];
            }
            if (m == NN - 1) {
                const float* g = G + (((size_t)(NN - 1)) * 4 + 3) * 3;
                a0 += g[0]; a1 += g[1]; a2 += g[2];
            }
            float* p = out + (size_t)idx * 3;
            p[0] += s * a0; p[1] += s * a1; p[2] += s * a2;
        }
        if (step < 3) grid_bar();   // updated pcl visible before next grad phase
        s *= 0.95f;
    }
}

// ================= launch =================
extern "C" void kernel_launch(void* const* d_in, const int* in_sizes, int n_in,
                              void* d_out, int out_size)
{
    const float* pcl = (const float*)d_in[0];
    const float* Wf1 = (const float*)d_in[1];
    const float* bf1 = (const float*)d_in[2];
    const float* Wf2 = (const float*)d_in[3];
    const float* bf2 = (const float*)d_in[4];
    const float* W0  = (const float*)d_in[5];
    const float* b0  = (const float*)d_in[6];
    const float* Wb  = (const float*)d_in[7];
    const float* bb  = (const float*)d_in[8];
    const float* Wo  = (const float*)d_in[9];
    const float* bo  = (const float*)d_in[10];
    float* out = (float*)d_out;

    cudaFuncSetAttribute(fused_denoise, cudaFuncAttributeMaxDynamicSharedMemorySize, SMEM_TOTAL);
    fused_denoise<<<GRID, THREADS, SMEM_TOTAL>>>(pcl, Wf1, bf1, Wf2, bf2, W0, b0,
                                                 Wb, bb, Wo, bo, out);
}

// round 10
// speedup vs baseline: 1.3821x; 1.1433x over previous
#include <cuda_runtime.h>
#include <cuda_bf16.h>
#include <cstdint>

// ---------------- problem constants ----------------
#define BN 2
#define NN 16384
#define BKS 136           // bf16 B row stride (elements): 272 B, conflict-free ldmatrix
#define GRID 296          // 148 SMs x 2 CTAs — all co-resident (grid barrier requirement)
#define THREADS 256
#define N_STRIPS_G (BN * NN * 4 / 16)   // 8192 grad warp strips
#define N_STRIPS_P (BN * NN / 16)       // 2048 precompute warp strips

// ---------------- device scratch ----------------
__device__ __align__(256) float g_gW0[BN * NN * 128];
__device__ __align__(256) float g_grad[BN * NN * 4 * 3];
__device__ __align__(256) __nv_bfloat16 g_Wb[2 * 128 * BKS];
__device__ __align__(256) __nv_bfloat16 g_Wf2T[128 * BKS];
__device__ __align__(256) __nv_bfloat16 g_W03T[128 * BKS];
__device__ unsigned g_ctr[4];
__device__ unsigned g_barcnt;
__device__ unsigned g_bargen;

// ================= helpers =================
__device__ __forceinline__ uint32_t smem_u32(const void* p) {
    uint32_t a;
    asm("{ .reg .u64 t; cvta.to.shared.u64 t, %1; cvt.u32.u64 %0, t; }" : "=r"(a) : "l"(p));
    return a;
}
__device__ __forceinline__ void ldsm4(uint32_t r[4], uint32_t addr) {
    asm volatile("ldmatrix.sync.aligned.m8n8.x4.shared.b16 {%0,%1,%2,%3}, [%4];"
                 : "=r"(r[0]), "=r"(r[1]), "=r"(r[2]), "=r"(r[3]) : "r"(addr));
}
__device__ __forceinline__ void ldsm2(uint32_t& r0, uint32_t& r1, uint32_t addr) {
    asm volatile("ldmatrix.sync.aligned.m8n8.x2.shared.b16 {%0,%1}, [%2];"
                 : "=r"(r0), "=r"(r1) : "r"(addr));
}
__device__ __forceinline__ void mma_bf16(float d[4], uint32_t a0, uint32_t a1,
                                         uint32_t a2, uint32_t a3,
                                         uint32_t b0, uint32_t b1) {
    asm volatile(
        "mma.sync.aligned.m16n8k16.row.col.f32.bf16.bf16.f32 "
        "{%0,%1,%2,%3}, {%4,%5,%6,%7}, {%8,%9}, {%0,%1,%2,%3};"
        : "+f"(d[0]), "+f"(d[1]), "+f"(d[2]), "+f"(d[3])
        : "r"(a0), "r"(a1), "r"(a2), "r"(a3), "r"(b0), "r"(b1));
}
__device__ __forceinline__ uint32_t packbf(float a, float b) {
    __nv_bfloat162 t = __floats2bfloat162_rn(a, b);
    return *(uint32_t*)&t;
}
__device__ __forceinline__ uint32_t hadd2u(uint32_t a, uint32_t b) {
    __nv_bfloat162 r = __hadd2(*(__nv_bfloat162*)&a, *(__nv_bfloat162*)&b);
    return *(uint32_t*)&r;
}
__device__ __forceinline__ uint32_t hmax2z(uint32_t a) {
    __nv_bfloat162 z = __float2bfloat162_rn(0.f);
    __nv_bfloat162 r = __hmax2(*(__nv_bfloat162*)&a, z);
    return *(uint32_t*)&r;
}

// sense-reversing software grid barrier (all GRID CTAs resident)
__device__ __forceinline__ void grid_bar() {
    __syncthreads();
    if (threadIdx.x == 0) {
        __threadfence();
        unsigned gen;
        asm volatile("ld.volatile.global.u32 %0, [%1];" : "=r"(gen) : "l"(&g_bargen));
        unsigned a = atomicAdd(&g_barcnt, 1u);
        if (a == GRID - 1u) {
            asm volatile("st.volatile.global.u32 [%0], %1;" :: "l"(&g_barcnt), "r"(0u) : "memory");
            __threadfence();
            atomicAdd(&g_bargen, 1u);
        } else {
            unsigned cur;
            do {
                asm volatile("ld.volatile.global.u32 %0, [%1];" : "=r"(cur) : "l"(&g_bargen));
            } while (cur == gen);
        }
        __threadfence();
    }
    __syncthreads();
}

// one n-half (64 cols) of a 16x128x128 warp GEMM; A fragments in regs
__device__ __forceinline__ void gemm_half(const uint32_t hA[16][2], uint32_t bHalf,
                                          float acc[8][4]) {
#pragma unroll
    for (int a = 0; a < 8; ++a)
#pragma unroll
        for (int i = 0; i < 4; ++i) acc[a][i] = 0.f;
#pragma unroll
    for (int s = 0; s < 8; ++s) {
        uint32_t a0 = hA[2 * s][0], a1 = hA[2 * s][1];
        uint32_t a2 = hA[2 * s + 1][0], a3 = hA[2 * s + 1][1];
#pragma unroll
        for (int jj = 0; jj < 4; ++jj) {
            uint32_t bf[4];
            ldsm4(bf, bHalf + (uint32_t)(jj * 16 * (BKS * 2)) + s * 32);
            mma_bf16(acc[2 * jj],     a0, a1, a2, a3, bf[0], bf[1]);
            mma_bf16(acc[2 * jj + 1], a0, a1, a2, a3, bf[2], bf[3]);
        }
    }
}

// ================= SMEM layout =================
#define BMAT_BYTES (128 * BKS * 2)          // 34816
#define BS_BYTES   (2 * BMAT_BYTES)         // 69632
#define WO_OFF     BS_BYTES                 // 16 rows x 136 x 2 = 4352
#define W03_OFF    (WO_OFF + 4352)          // 128 rows x 24 x 2 = 6144
#define BB2_OFF    (W03_OFF + 6144)         // 128 u32 = 512
#define MISC_OFF   (BB2_OFF + 512)          // 768 floats = 3072
#define SMEM_TOTAL (MISC_OFF + 3072)        // 83712 -> 2 CTAs/SM (167424)

// ================= the fused persistent kernel =================
__global__ __launch_bounds__(THREADS, 2)
void fused_denoise(const float* __restrict__ pcl,
                   const float* __restrict__ Wf1, const float* __restrict__ bf1,
                   const float* __restrict__ Wf2, const float* __restrict__ bf2,
                   const float* __restrict__ W0,  const float* __restrict__ b0,
                   const float* __restrict__ Wb,  const float* __restrict__ bb,
                   const float* __restrict__ Wo,  const float* __restrict__ bo,
                   float* __restrict__ out)
{
    extern __shared__ __align__(256) char smc[];
    const int t    = threadIdx.x;
    const int lane = t & 31;
    const int w    = t >> 5;
    const int gtid = blockIdx.x * THREADS + t;

    char* B_s = smc;
    __nv_bfloat16* Wo_s  = (__nv_bfloat16*)(smc + WO_OFF);    // [16 n][136 k]
    __nv_bfloat16* W03_s = (__nv_bfloat16*)(smc + W03_OFF);   // [128 n][24 k]
    uint32_t* shBB2 = (uint32_t*)(smc + BB2_OFF);             // packed bb pairs
    float* shWf1 = (float*)(smc + MISC_OFF);
    float* shbf1 = shWf1 + 384;
    float* shbf2 = shbf1 + 128;
    float* shb0  = shbf2 + 128;

    // ---------- phase 0: convert weights to bf16 transposed/padded; reset counters ----------
    for (int idx = gtid; idx < 4 * 128 * 128; idx += GRID * THREADS) {
        int seg = idx >> 14;
        int rem = idx & 16383;
        int n = rem >> 7, k = rem & 127;
        if (seg < 2) {
            g_Wb[seg * 128 * BKS + n * BKS + k] = __float2bfloat16(Wb[seg * 16384 + k * 128 + n]);
        } else if (seg == 2) {
            g_Wf2T[n * BKS + k] = __float2bfloat16(Wf2[k * 128 + n]);
        } else {
            g_W03T[n * BKS + k] = __float2bfloat16(W0[(3 + k) * 128 + n]);
        }
    }
    if (blockIdx.x == 0 && t < 4) g_ctr[t] = 0;
    grid_bar();

    // ---------- stage SMEM: small weights, Wo tile, W0[:3] tile, bb pairs; precompute B ----------
    for (int i = t; i < 384; i += THREADS) shWf1[i] = Wf1[i];
    if (t < 128) { shbf1[t] = bf1[t]; shbf2[t] = bf2[t]; shb0[t] = b0[t]; }
    for (int i = t; i < 16 * 128; i += THREADS) {       // Wo^T padded to 16 rows
        int n = i >> 7, k = i & 127;
        Wo_s[n * 136 + k] = (n < 3) ? __float2bfloat16(Wo[k * 3 + n]) : __nv_bfloat16(0.f);
    }
    for (int i = t; i < 128 * 16; i += THREADS) {       // (W0[:3])^T padded to k=16
        int n = i >> 4, k = i & 15;
        W03_s[n * 24 + k] = (k < 3) ? __float2bfloat16(W0[k * 128 + n]) : __nv_bfloat16(0.f);
    }
    if (t < 128) shBB2[t] = packbf(bb[2 * t], bb[2 * t + 1]);
    {
        const uint4* s1 = (const uint4*)g_Wf2T;
        const uint4* s2 = (const uint4*)g_W03T;
        uint4* d1 = (uint4*)B_s;
        uint4* d2 = (uint4*)(B_s + BMAT_BYTES);
        for (int i = t; i < BMAT_BYTES / 16; i += THREADS) { d1[i] = s1[i]; d2[i] = s2[i]; }
    }
    __syncthreads();

    const int rgrp = lane >> 2;
    const int cpos = (lane & 3) * 2;
    const uint32_t bAddr = smem_u32(B_s)
        + (uint32_t)(((lane & 7) + ((lane >> 4) << 3)) * (BKS * 2))
        + (uint32_t)(((lane >> 3) & 1) << 4);
    const uint32_t addrWo = smem_u32(Wo_s)
        + (uint32_t)(((lane & 7) + ((lane >> 4) << 3)) * 272)
        + (uint32_t)(((lane >> 3) & 1) << 4);
    const uint32_t addr03 = smem_u32(W03_s)
        + (uint32_t)(((lane & 7) + ((lane >> 4) << 3)) * 48)
        + (uint32_t)(((lane >> 3) & 1) << 4);

    // ---------- phase 1: precompute (one 16-point strip per warp, static) ----------
    {
        const int sp = blockIdx.x * 8 + w;
        if (sp < N_STRIPS_P) {
            const int b  = sp >> 10;
            const int p0 = (sp & 1023) * 16;
            const float* pclb = pcl + ((size_t)b * NN + p0) * 3;
            float* outb = out + ((size_t)b * NN + p0) * 3;
            for (int i = lane; i < 48; i += 32) outb[i] = pclb[i];

            float xl0 = pclb[rgrp * 3 + 0], xl1 = pclb[rgrp * 3 + 1], xl2 = pclb[rgrp * 3 + 2];
            float xh0 = pclb[(rgrp + 8) * 3 + 0], xh1 = pclb[(rgrp + 8) * 3 + 1], xh2 = pclb[(rgrp + 8) * 3 + 2];

            uint32_t hA[16][2];
#pragma unroll
            for (int j = 0; j < 16; ++j) {
                int c = j * 8 + cpos;
                float w0a = shWf1[c],     w1a = shWf1[128 + c],     w2a = shWf1[256 + c],     ba  = shbf1[c];
                float w0b = shWf1[c + 1], w1b = shWf1[128 + c + 1], w2b = shWf1[256 + c + 1], bbv = shbf1[c + 1];
                float vl0 = fmaf(xl0, w0a, fmaf(xl1, w1a, fmaf(xl2, w2a, ba)));
                float vl1 = fmaf(xl0, w0b, fmaf(xl1, w1b, fmaf(xl2, w2b, bbv)));
                float vh0 = fmaf(xh0, w0a, fmaf(xh1, w1a, fmaf(xh2, w2a, ba)));
                float vh1 = fmaf(xh0, w0b, fmaf(xh1, w1b, fmaf(xh2, w2b, bbv)));
                hA[j][0] = packbf(fmaxf(vl0, 0.f), fmaxf(vl1, 0.f));
                hA[j][1] = packbf(fmaxf(vh0, 0.f), fmaxf(vh1, 0.f));
            }

            // GEMM1: feat = h1 @ Wf2 + bf2 (no relu)
            {
                uint32_t hN[16][2];
#pragma unroll
                for (int half = 0; half < 2; ++half) {
                    float acc[8][4];
                    gemm_half(hA, bAddr + (uint32_t)(half * 64 * (BKS * 2)), acc);
#pragma unroll
                    for (int a = 0; a < 8; ++a) {
                        int j = half * 8 + a;
                        int c = j * 8 + cpos;
                        float b0v = shbf2[c], b1v = shbf2[c + 1];
                        hN[j][0] = packbf(acc[a][0] + b0v, acc[a][1] + b1v);
                        hN[j][1] = packbf(acc[a][2] + b0v, acc[a][3] + b1v);
                    }
                }
#pragma unroll
                for (int j = 0; j < 16; ++j) { hA[j][0] = hN[j][0]; hA[j][1] = hN[j][1]; }
            }

            // GEMM2: gW0 = feat @ W0[3:] + b0
            {
                float* gb = g_gW0 + ((size_t)b * NN + p0) * 128;
#pragma unroll
                for (int half = 0; half < 2; ++half) {
                    float acc[8][4];
                    gemm_half(hA, bAddr + (uint32_t)BMAT_BYTES + (uint32_t)(half * 64 * (BKS * 2)), acc);
#pragma unroll
                    for (int a = 0; a < 8; ++a) {
                        int j = half * 8 + a;
                        int c = j * 8 + cpos;
                        float b0v = shb0[c], b1v = shb0[c + 1];
                        *(float2*)(gb + (size_t)rgrp * 128 + c)       = make_float2(acc[a][0] + b0v, acc[a][1] + b1v);
                        *(float2*)(gb + (size_t)(rgrp + 8) * 128 + c) = make_float2(acc[a][2] + b0v, acc[a][3] + b1v);
                    }
                }
            }
        }
    }
    grid_bar();

    // ---------- reload B_s with Wb0, Wb1 ----------
    {
        const uint4* src = (const uint4*)g_Wb;
        uint4* dst = (uint4*)B_s;
        for (int i = t; i < BS_BYTES / 16; i += THREADS) dst[i] = src[i];
    }
    __syncthreads();

    const float bo0 = bo[0], bo1 = bo[1], bo2 = bo[2];
    float s = 0.2f;

    // ---------- 4 denoise steps ----------
    for (int step = 0; step < 4; ++step) {
        // ---- grad phase: dynamic per-warp strips ----
        unsigned nxt = 0, strip;
        if (lane == 0) nxt = atomicAdd(&g_ctr[step], 1u);
        strip = __shfl_sync(0xffffffffu, nxt, 0);

        while (strip < N_STRIPS_G) {
            if (lane == 0) nxt = atomicAdd(&g_ctr[step], 1u);

            const int b  = (int)(strip >> 12);
            const int p0 = (int)(strip & 4095) * 4;

            int n_lo = p0 + (rgrp >> 2), q_lo = rgrp & 3;
            int n_hi = p0 + ((rgrp + 8) >> 2), q_hi = (rgrp + 8) & 3;
            int m_lo = n_lo + q_lo - 2; m_lo = m_lo < 0 ? 0 : (m_lo > NN - 1 ? NN - 1 : m_lo);
            int m_hi = n_hi + q_hi - 2; m_hi = m_hi < 0 ? 0 : (m_hi > NN - 1 ? NN - 1 : m_hi);

            const float* pcl_b = out + (size_t)b * NN * 3;
            const float* pn_b  = pcl + (size_t)b * NN * 3;
            float cl0 = pcl_b[m_lo * 3 + 0] - pn_b[n_lo * 3 + 0];
            float cl1 = pcl_b[m_lo * 3 + 1] - pn_b[n_lo * 3 + 1];
            float cl2 = pcl_b[m_lo * 3 + 2] - pn_b[n_lo * 3 + 2];
            float ch0 = pcl_b[m_hi * 3 + 0] - pn_b[n_hi * 3 + 0];
            float ch1 = pcl_b[m_hi * 3 + 1] - pn_b[n_hi * 3 + 1];
            float ch2 = pcl_b[m_hi * 3 + 2] - pn_b[n_hi * 3 + 2];

            const float* gwl = g_gW0 + ((size_t)b * NN + n_lo) * 128;
            const float* gwh = g_gW0 + ((size_t)b * NN + n_hi) * 128;

            // A fragments for centered (k=3 padded to 16): a0 rows rgrp, a1 rows rgrp+8
            uint32_t caL, caH;
            {
                int role = lane & 3;
                caL = role == 0 ? packbf(cl0, cl1) : (role == 1 ? packbf(cl2, 0.f) : 0u);
                caH = role == 0 ? packbf(ch0, ch1) : (role == 1 ? packbf(ch2, 0.f) : 0u);
            }
            const uint32_t z2 = 0;

            // h0 = relu(centered @ W0[:3] + gW0) via MMA, epilogue per 16-col tile
            uint32_t hA[16][2];
#pragma unroll
            for (int jj = 0; jj < 8; ++jj) {
                uint32_t bf[4];
                ldsm4(bf, addr03 + (uint32_t)(jj * 768));
                float a0[4] = {0.f, 0.f, 0.f, 0.f}, a1[4] = {0.f, 0.f, 0.f, 0.f};
                mma_bf16(a0, caL, caH, z2, z2, bf[0], bf[1]);
                mma_bf16(a1, caL, caH, z2, z2, bf[2], bf[3]);
                int c = jj * 16 + cpos;
                float2 gl0 = *(const float2*)(gwl + c);
                float2 gh0 = *(const float2*)(gwh + c);
                float2 gl1 = *(const float2*)(gwl + c + 8);
                float2 gh1 = *(const float2*)(gwh + c + 8);
                hA[2 * jj][0]     = packbf(fmaxf(a0[0] + gl0.x, 0.f), fmaxf(a0[1] + gl0.y, 0.f));
                hA[2 * jj][1]     = packbf(fmaxf(a0[2] + gh0.x, 0.f), fmaxf(a0[3] + gh0.y, 0.f));
                hA[2 * jj + 1][0] = packbf(fmaxf(a1[0] + gl1.x, 0.f), fmaxf(a1[1] + gl1.y, 0.f));
                hA[2 * jj + 1][1] = packbf(fmaxf(a1[2] + gh1.x, 0.f), fmaxf(a1[3] + gh1.y, 0.f));
            }

            // two residual blocks, bf16x2 epilogues
#pragma unroll
            for (int blk = 0; blk < 2; ++blk) {
                uint32_t bBlk = bAddr + (uint32_t)(blk * BMAT_BYTES);
                uint32_t hN[16][2];
#pragma unroll
                for (int half = 0; half < 2; ++half) {
                    float acc[8][4];
                    gemm_half(hA, bBlk + (uint32_t)(half * 64 * (BKS * 2)), acc);
#pragma unroll
                    for (int a = 0; a < 8; ++a) {
                        int j = half * 8 + a;
                        uint32_t bbp = shBB2[blk * 64 + j * 4 + (lane & 3)];
                        uint32_t lo = packbf(acc[a][0], acc[a][1]);
                        uint32_t hi = packbf(acc[a][2], acc[a][3]);
                        hN[j][0] = hadd2u(hA[j][0], hmax2z(hadd2u(lo, bbp)));
                        hN[j][1] = hadd2u(hA[j][1], hmax2z(hadd2u(hi, bbp)));
                    }
                }
#pragma unroll
                for (int j = 0; j < 16; ++j) { hA[j][0] = hN[j][0]; hA[j][1] = hN[j][1]; }
            }

            // grad = h @ Wo + bo via MMA over padded 16-col Wo tile
            {
                float accW[4] = {0.f, 0.f, 0.f, 0.f};
#pragma unroll
                for (int s8 = 0; s8 < 8; ++s8) {
                    uint32_t b0f, b1f;
                    ldsm2(b0f, b1f, addrWo + (uint32_t)(s8 * 32));
                    mma_bf16(accW, hA[2 * s8][0], hA[2 * s8][1],
                             hA[2 * s8 + 1][0], hA[2 * s8 + 1][1], b0f, b1f);
                }
                float* gp0 = g_grad + (((size_t)b * NN + p0) * 4 + rgrp) * 3;
                float* gp1 = gp0 + 8 * 3;
                int role = lane & 3;
                if (role == 0) {
                    gp0[0] = accW[0] + bo0; gp0[1] = accW[1] + bo1;
                    gp1[0] = accW[2] + bo0; gp1[1] = accW[3] + bo1;
                } else if (role == 1) {
                    gp0[2] = accW[0] + bo2;
                    gp1[2] = accW[2] + bo2;
                }
            }

            strip = __shfl_sync(0xffffffffu, nxt, 0);
        }
        grid_bar();   // grads visible

        // ---- gather phase: full-grid, one point per thread ----
        for (int idx = gtid; idx < BN * NN; idx += GRID * THREADS) {
            int b = idx / NN, m = idx - b * NN;
            const float* G = g_grad + (size_t)b * NN * 12;
            float a0 = 0.f, a1 = 0.f, a2 = 0.f;
#pragma unroll
            for (int k = 0; k < 4; ++k) {
                int n = m + 2 - k;
                if (n >= 0 && n < NN) {
                    const float* g = G + ((size_t)n * 4 + k) * 3;
                    a0 += g[0]; a1 += g[1]; a2 += g[2];
                }
            }
            if (m == 0) {
                a0 += G[0] + G[3] + G[12];
                a1 += G[1] + G[4] + G[13];
                a2 += G[2] + G[5] + G[14];
            }
            if (m == NN - 1) {
                const float* g = G + (((size_t)(NN - 1)) * 4 + 3) * 3;
                a0 += g[0]; a1 += g[1]; a2 += g[2];
            }
            float* p = out + (size_t)idx * 3;
            p[0] += s * a0; p[1] += s * a1; p[2] += s * a2;
        }
        if (step < 3) grid_bar();
        s *= 0.95f;
    }
}

// ================= launch =================
extern "C" void kernel_launch(void* const* d_in, const int* in_sizes, int n_in,
                              void* d_out, int out_size)
{
    const float* pcl = (const float*)d_in[0];
    const float* Wf1 = (const float*)d_in[1];
    const float* bf1 = (const float*)d_in[2];
    const float* Wf2 = (const float*)d_in[3];
    const float* bf2 = (const float*)d_in[4];
    const float* W0  = (const float*)d_in[5];
    const float* b0  = (const float*)d_in[6];
    const float* Wb  = (const float*)d_in[7];
    const float* bb  = (const float*)d_in[8];
    const float* Wo  = (const float*)d_in[9];
    const float* bo  = (const float*)d_in[10];
    float* out = (float*)d_out;

    cudaFuncSetAttribute(fused_denoise, cudaFuncAttributeMaxDynamicSharedMemorySize, SMEM_TOTAL);
    fused_denoise<<<GRID, THREADS, SMEM_TOTAL>>>(pcl, Wf1, bf1, Wf2, bf2, W0, b0,
                                                 Wb, bb, Wo, bo, out);
}

// round 11
// speedup vs baseline: 1.4131x; 1.0224x over previous
#include <cuda_runtime.h>
#include <cuda_fp16.h>
#include <cstdint>

// ---------------- problem constants ----------------
#define BN 2
#define NN 16384
#define BKS 136           // fp16 B row stride (elements): 272 B, conflict-free ldmatrix
#define GRID 296          // 148 SMs x 2 CTAs — all co-resident (grid barrier requirement)
#define THREADS 256
#define N_STRIPS_G (BN * NN * 4 / 16)   // 8192 grad warp strips
#define N_STRIPS_P (BN * NN / 16)       // 2048 precompute warp strips

// ---------------- device scratch ----------------
__device__ __align__(256) uint32_t g_gW0h[BN * NN * 64];   // feat@W0[3:]+b0, packed fp16 pairs
__device__ __align__(256) float g_grad[BN * NN * 4 * 3];
__device__ __align__(256) __half g_Wb[2 * 128 * BKS];
__device__ __align__(256) __half g_Wf2T[128 * BKS];
__device__ __align__(256) __half g_W03T[128 * BKS];
__device__ unsigned g_ctr[4];
__device__ unsigned g_barcnt;
__device__ unsigned g_bargen;

// ================= helpers =================
__device__ __forceinline__ uint32_t smem_u32(const void* p) {
    uint32_t a;
    asm("{ .reg .u64 t; cvta.to.shared.u64 t, %1; cvt.u32.u64 %0, t; }" : "=r"(a) : "l"(p));
    return a;
}
__device__ __forceinline__ void ldsm4(uint32_t r[4], uint32_t addr) {
    asm volatile("ldmatrix.sync.aligned.m8n8.x4.shared.b16 {%0,%1,%2,%3}, [%4];"
                 : "=r"(r[0]), "=r"(r[1]), "=r"(r[2]), "=r"(r[3]) : "r"(addr));
}
__device__ __forceinline__ void ldsm2(uint32_t& r0, uint32_t& r1, uint32_t addr) {
    asm volatile("ldmatrix.sync.aligned.m8n8.x2.shared.b16 {%0,%1}, [%2];"
                 : "=r"(r0), "=r"(r1) : "r"(addr));
}
// f16 inputs, f16 accumulators (D==C, packed pairs)
__device__ __forceinline__ void mma_f16(uint32_t& d0, uint32_t& d1,
                                        uint32_t a0, uint32_t a1, uint32_t a2, uint32_t a3,
                                        uint32_t b0, uint32_t b1) {
    asm volatile(
        "mma.sync.aligned.m16n8k16.row.col.f16.f16.f16.f16 "
        "{%0,%1}, {%2,%3,%4,%5}, {%6,%7}, {%0,%1};"
        : "+r"(d0), "+r"(d1)
        : "r"(a0), "r"(a1), "r"(a2), "r"(a3), "r"(b0), "r"(b1));
}
// f16 inputs, f32 accumulators (for the Wo grad GEMM)
__device__ __forceinline__ void mma_f32(float d[4], uint32_t a0, uint32_t a1,
                                        uint32_t a2, uint32_t a3,
                                        uint32_t b0, uint32_t b1) {
    asm volatile(
        "mma.sync.aligned.m16n8k16.row.col.f32.f16.f16.f32 "
        "{%0,%1,%2,%3}, {%4,%5,%6,%7}, {%8,%9}, {%0,%1,%2,%3};"
        : "+f"(d[0]), "+f"(d[1]), "+f"(d[2]), "+f"(d[3])
        : "r"(a0), "r"(a1), "r"(a2), "r"(a3), "r"(b0), "r"(b1));
}
__device__ __forceinline__ uint32_t packhf(float a, float b) {
    __half2 t = __floats2half2_rn(a, b);
    return *(uint32_t*)&t;
}
__device__ __forceinline__ uint32_t hadd2u(uint32_t a, uint32_t b) {
    __half2 r = __hadd2(*(__half2*)&a, *(__half2*)&b);
    return *(uint32_t*)&r;
}
__device__ __forceinline__ uint32_t hmax2z(uint32_t a) {
    __half2 z = __floats2half2_rn(0.f, 0.f);
    __half2 r = __hmax2(*(__half2*)&a, z);
    return *(uint32_t*)&r;
}
__device__ __forceinline__ float2 unpackhf(uint32_t u) {
    return __half22float2(*(__half2*)&u);
}

// sense-reversing software grid barrier (all GRID CTAs resident)
__device__ __forceinline__ void grid_bar() {
    __syncthreads();
    if (threadIdx.x == 0) {
        __threadfence();
        unsigned gen;
        asm volatile("ld.volatile.global.u32 %0, [%1];" : "=r"(gen) : "l"(&g_bargen));
        unsigned a = atomicAdd(&g_barcnt, 1u);
        if (a == GRID - 1u) {
            asm volatile("st.volatile.global.u32 [%0], %1;" :: "l"(&g_barcnt), "r"(0u) : "memory");
            __threadfence();
            atomicAdd(&g_bargen, 1u);
        } else {
            unsigned cur;
            do {
                asm volatile("ld.volatile.global.u32 %0, [%1];" : "=r"(cur) : "l"(&g_bargen));
            } while (cur == gen);
        }
        __threadfence();
    }
    __syncthreads();
}

// full-width 16x128x128 warp GEMM, fp16 accumulators (acc[16][2] packed pairs)
__device__ __forceinline__ void gemm_f16(const uint32_t hA[16][2], uint32_t bBase,
                                         uint32_t acc[16][2]) {
#pragma unroll
    for (int j = 0; j < 16; ++j) { acc[j][0] = 0u; acc[j][1] = 0u; }
#pragma unroll
    for (int s = 0; s < 8; ++s) {
        uint32_t a0 = hA[2 * s][0], a1 = hA[2 * s][1];
        uint32_t a2 = hA[2 * s + 1][0], a3 = hA[2 * s + 1][1];
#pragma unroll
        for (int jj = 0; jj < 8; ++jj) {
            uint32_t bf[4];
            ldsm4(bf, bBase + (uint32_t)(jj * 16 * (BKS * 2)) + s * 32);
            mma_f16(acc[2 * jj][0],     acc[2 * jj][1],     a0, a1, a2, a3, bf[0], bf[1]);
            mma_f16(acc[2 * jj + 1][0], acc[2 * jj + 1][1], a0, a1, a2, a3, bf[2], bf[3]);
        }
    }
}

// ================= SMEM layout =================
#define BMAT_BYTES (128 * BKS * 2)          // 34816
#define BS_BYTES   (2 * BMAT_BYTES)         // 69632
#define WO_OFF     BS_BYTES                 // 16 x 136 x 2 = 4352
#define W03_OFF    (WO_OFF + 4352)          // 128 x 24 x 2 = 6144
#define BB2_OFF    (W03_OFF + 6144)         // 128 u32
#define BF2P_OFF   (BB2_OFF + 512)          // 64 u32
#define B0P_OFF    (BF2P_OFF + 256)         // 64 u32
#define MISC_OFF   (B0P_OFF + 256)          // Wf1 384f + bf1 128f
#define SMEM_TOTAL (MISC_OFF + 2048)        // 83200 -> 2 CTAs/SM

// ================= the fused persistent kernel =================
__global__ __launch_bounds__(THREADS, 2)
void fused_denoise(const float* __restrict__ pcl,
                   const float* __restrict__ Wf1, const float* __restrict__ bf1,
                   const float* __restrict__ Wf2, const float* __restrict__ bf2,
                   const float* __restrict__ W0,  const float* __restrict__ b0,
                   const float* __restrict__ Wb,  const float* __restrict__ bb,
                   const float* __restrict__ Wo,  const float* __restrict__ bo,
                   float* __restrict__ out)
{
    extern __shared__ __align__(256) char smc[];
    const int t    = threadIdx.x;
    const int lane = t & 31;
    const int w    = t >> 5;
    const int gtid = blockIdx.x * THREADS + t;

    char* B_s = smc;
    __half* Wo_s  = (__half*)(smc + WO_OFF);     // [16 n][136 k]
    __half* W03_s = (__half*)(smc + W03_OFF);    // [128 n][24 k]
    uint32_t* shBB2  = (uint32_t*)(smc + BB2_OFF);
    uint32_t* shBF2P = (uint32_t*)(smc + BF2P_OFF);
    uint32_t* shB0P  = (uint32_t*)(smc + B0P_OFF);
    float* shWf1 = (float*)(smc + MISC_OFF);
    float* shbf1 = shWf1 + 384;

    // ---------- phase 0: convert weights to fp16 transposed/padded; reset counters ----------
    for (int idx = gtid; idx < 4 * 128 * 128; idx += GRID * THREADS) {
        int seg = idx >> 14;
        int rem = idx & 16383;
        int n = rem >> 7, k = rem & 127;
        if (seg < 2) {
            g_Wb[seg * 128 * BKS + n * BKS + k] = __float2half(Wb[seg * 16384 + k * 128 + n]);
        } else if (seg == 2) {
            g_Wf2T[n * BKS + k] = __float2half(Wf2[k * 128 + n]);
        } else {
            g_W03T[n * BKS + k] = __float2half(W0[(3 + k) * 128 + n]);
        }
    }
    if (blockIdx.x == 0 && t < 4) g_ctr[t] = 0;
    grid_bar();

    // ---------- stage SMEM ----------
    for (int i = t; i < 384; i += THREADS) shWf1[i] = Wf1[i];
    if (t < 128) shbf1[t] = bf1[t];
    for (int i = t; i < 16 * 128; i += THREADS) {        // Wo^T padded to 16 rows
        int n = i >> 7, k = i & 127;
        Wo_s[n * 136 + k] = (n < 3) ? __float2half(Wo[k * 3 + n]) : __half(0.f);
    }
    for (int i = t; i < 128 * 16; i += THREADS) {        // (W0[:3])^T padded to k=16
        int n = i >> 4, k = i & 15;
        W03_s[n * 24 + k] = (k < 3) ? __float2half(W0[k * 128 + n]) : __half(0.f);
    }
    if (t < 128) shBB2[t] = packhf(bb[2 * t], bb[2 * t + 1]);
    if (t < 64)  { shBF2P[t] = packhf(bf2[2 * t], bf2[2 * t + 1]);
                   shB0P[t]  = packhf(b0[2 * t],  b0[2 * t + 1]); }
    {
        const uint4* s1 = (const uint4*)g_Wf2T;
        const uint4* s2 = (const uint4*)g_W03T;
        uint4* d1 = (uint4*)B_s;
        uint4* d2 = (uint4*)(B_s + BMAT_BYTES);
        for (int i = t; i < BMAT_BYTES / 16; i += THREADS) { d1[i] = s1[i]; d2[i] = s2[i]; }
    }
    __syncthreads();

    const int rgrp = lane >> 2;
    const int cpos = (lane & 3) * 2;
    const int role = lane & 3;
    const uint32_t bAddr = smem_u32(B_s)
        + (uint32_t)(((lane & 7) + ((lane >> 4) << 3)) * (BKS * 2))
        + (uint32_t)(((lane >> 3) & 1) << 4);
    const uint32_t addrWo = smem_u32(Wo_s)
        + (uint32_t)(((lane & 7) + ((lane >> 4) << 3)) * 272)
        + (uint32_t)(((lane >> 3) & 1) << 4);
    const uint32_t addr03 = smem_u32(W03_s)
        + (uint32_t)(((lane & 7) + ((lane >> 4) << 3)) * 48)
        + (uint32_t)(((lane >> 3) & 1) << 4);

    // ---------- phase 1: precompute (one 16-point strip per warp, static) ----------
    {
        const int sp = blockIdx.x * 8 + w;
        if (sp < N_STRIPS_P) {
            const int b  = sp >> 10;
            const int p0 = (sp & 1023) * 16;
            const float* pclb = pcl + ((size_t)b * NN + p0) * 3;
            float* outb = out + ((size_t)b * NN + p0) * 3;
            for (int i = lane; i < 48; i += 32) outb[i] = pclb[i];

            float xl0 = pclb[rgrp * 3 + 0], xl1 = pclb[rgrp * 3 + 1], xl2 = pclb[rgrp * 3 + 2];
            float xh0 = pclb[(rgrp + 8) * 3 + 0], xh1 = pclb[(rgrp + 8) * 3 + 1], xh2 = pclb[(rgrp + 8) * 3 + 2];

            uint32_t hA[16][2];
#pragma unroll
            for (int j = 0; j < 16; ++j) {
                int c = j * 8 + cpos;
                float w0a = shWf1[c],     w1a = shWf1[128 + c],     w2a = shWf1[256 + c],     ba  = shbf1[c];
                float w0b = shWf1[c + 1], w1b = shWf1[128 + c + 1], w2b = shWf1[256 + c + 1], bbv = shbf1[c + 1];
                float vl0 = fmaf(xl0, w0a, fmaf(xl1, w1a, fmaf(xl2, w2a, ba)));
                float vl1 = fmaf(xl0, w0b, fmaf(xl1, w1b, fmaf(xl2, w2b, bbv)));
                float vh0 = fmaf(xh0, w0a, fmaf(xh1, w1a, fmaf(xh2, w2a, ba)));
                float vh1 = fmaf(xh0, w0b, fmaf(xh1, w1b, fmaf(xh2, w2b, bbv)));
                hA[j][0] = packhf(fmaxf(vl0, 0.f), fmaxf(vl1, 0.f));
                hA[j][1] = packhf(fmaxf(vh0, 0.f), fmaxf(vh1, 0.f));
            }

            uint32_t acc[16][2];

            // GEMM1: feat = h1 @ Wf2 + bf2 (no relu), in-place into hA
            gemm_f16(hA, bAddr, acc);
#pragma unroll
            for (int j = 0; j < 16; ++j) {
                uint32_t bp = shBF2P[j * 4 + role];
                hA[j][0] = hadd2u(acc[j][0], bp);
                hA[j][1] = hadd2u(acc[j][1], bp);
            }

            // GEMM2: gW0 = feat @ W0[3:] + b0 -> packed fp16 pairs in global
            gemm_f16(hA, bAddr + (uint32_t)BMAT_BYTES, acc);
            {
                uint32_t* gb = g_gW0h + ((size_t)b * NN + p0) * 64;
#pragma unroll
                for (int j = 0; j < 16; ++j) {
                    uint32_t bp = shB0P[j * 4 + role];
                    gb[(size_t)rgrp * 64 + j * 4 + role]       = hadd2u(acc[j][0], bp);
                    gb[(size_t)(rgrp + 8) * 64 + j * 4 + role] = hadd2u(acc[j][1], bp);
                }
            }
        }
    }
    grid_bar();

    // ---------- reload B_s with Wb0, Wb1; preload Wo fragments ----------
    {
        const uint4* src = (const uint4*)g_Wb;
        uint4* dst = (uint4*)B_s;
        for (int i = t; i < BS_BYTES / 16; i += THREADS) dst[i] = src[i];
    }
    __syncthreads();

    uint32_t woF[8][2];
#pragma unroll
    for (int s8 = 0; s8 < 8; ++s8) ldsm2(woF[s8][0], woF[s8][1], addrWo + (uint32_t)(s8 * 32));

    const float bo0 = bo[0], bo1 = bo[1], bo2 = bo[2];
    float s = 0.2f;

    // ---------- 4 denoise steps ----------
    for (int step = 0; step < 4; ++step) {
        // ---- grad phase: dynamic per-warp strips ----
        unsigned nxt = 0, strip;
        if (lane == 0) nxt = atomicAdd(&g_ctr[step], 1u);
        strip = __shfl_sync(0xffffffffu, nxt, 0);

        while (strip < N_STRIPS_G) {
            if (lane == 0) nxt = atomicAdd(&g_ctr[step], 1u);

            const int b  = (int)(strip >> 12);
            const int p0 = (int)(strip & 4095) * 4;

            int n_lo = p0 + (rgrp >> 2), q_lo = rgrp & 3;
            int n_hi = p0 + ((rgrp + 8) >> 2), q_hi = (rgrp + 8) & 3;
            int m_lo = n_lo + q_lo - 2; m_lo = m_lo < 0 ? 0 : (m_lo > NN - 1 ? NN - 1 : m_lo);
            int m_hi = n_hi + q_hi - 2; m_hi = m_hi < 0 ? 0 : (m_hi > NN - 1 ? NN - 1 : m_hi);

            const float* pcl_b = out + (size_t)b * NN * 3;
            const float* pn_b  = pcl + (size_t)b * NN * 3;
            float cl0 = pcl_b[m_lo * 3 + 0] - pn_b[n_lo * 3 + 0];
            float cl1 = pcl_b[m_lo * 3 + 1] - pn_b[n_lo * 3 + 1];
            float cl2 = pcl_b[m_lo * 3 + 2] - pn_b[n_lo * 3 + 2];
            float ch0 = pcl_b[m_hi * 3 + 0] - pn_b[n_hi * 3 + 0];
            float ch1 = pcl_b[m_hi * 3 + 1] - pn_b[n_hi * 3 + 1];
            float ch2 = pcl_b[m_hi * 3 + 2] - pn_b[n_hi * 3 + 2];

            const uint32_t* gwl = g_gW0h + ((size_t)b * NN + n_lo) * 64;
            const uint32_t* gwh = g_gW0h + ((size_t)b * NN + n_hi) * 64;

            // A fragments for centered (k=3 padded to 16)
            uint32_t caL, caH;
            caL = role == 0 ? packhf(cl0, cl1) : (role == 1 ? packhf(cl2, 0.f) : 0u);
            caH = role == 0 ? packhf(ch0, ch1) : (role == 1 ? packhf(ch2, 0.f) : 0u);
            const uint32_t z2 = 0;

            // h0 = relu(centered @ W0[:3] + gW0) via fp16-acc MMA
            uint32_t hA[16][2];
#pragma unroll
            for (int jj = 0; jj < 8; ++jj) {
                uint32_t bf[4];
                ldsm4(bf, addr03 + (uint32_t)(jj * 768));
                uint32_t d00 = 0, d01 = 0, d10 = 0, d11 = 0;
                mma_f16(d00, d01, caL, caH, z2, z2, bf[0], bf[1]);
                mma_f16(d10, d11, caL, caH, z2, z2, bf[2], bf[3]);
                int pi = jj * 8 + role;
                hA[2 * jj][0]     = hmax2z(hadd2u(d00, gwl[pi]));
                hA[2 * jj][1]     = hmax2z(hadd2u(d01, gwh[pi]));
                hA[2 * jj + 1][0] = hmax2z(hadd2u(d10, gwl[pi + 4]));
                hA[2 * jj + 1][1] = hmax2z(hadd2u(d11, gwh[pi + 4]));
            }

            // two residual blocks, fp16 acc, in-place epilogues
#pragma unroll
            for (int blk = 0; blk < 2; ++blk) {
                uint32_t acc[16][2];
                gemm_f16(hA, bAddr + (uint32_t)(blk * BMAT_BYTES), acc);
#pragma unroll
                for (int j = 0; j < 16; ++j) {
                    uint32_t bbp = shBB2[blk * 64 + j * 4 + role];
                    hA[j][0] = hadd2u(hA[j][0], hmax2z(hadd2u(acc[j][0], bbp)));
                    hA[j][1] = hadd2u(hA[j][1], hmax2z(hadd2u(acc[j][1], bbp)));
                }
            }

            // grad = h @ Wo + bo via fp32-acc MMA with preloaded Wo fragments
            {
                float accW[4] = {0.f, 0.f, 0.f, 0.f};
#pragma unroll
                for (int s8 = 0; s8 < 8; ++s8)
                    mma_f32(accW, hA[2 * s8][0], hA[2 * s8][1],
                            hA[2 * s8 + 1][0], hA[2 * s8 + 1][1], woF[s8][0], woF[s8][1]);
                float* gp0 = g_grad + (((size_t)b * NN + p0) * 4 + rgrp) * 3;
                float* gp1 = gp0 + 8 * 3;
                if (role == 0) {
                    gp0[0] = accW[0] + bo0; gp0[1] = accW[1] + bo1;
                    gp1[0] = accW[2] + bo0; gp1[1] = accW[3] + bo1;
                } else if (role == 1) {
                    gp0[2] = accW[0] + bo2;
                    gp1[2] = accW[2] + bo2;
                }
            }

            strip = __shfl_sync(0xffffffffu, nxt, 0);
        }
        grid_bar();   // grads visible

        // ---- gather phase: full-grid, one point per thread ----
        for (int idx = gtid; idx < BN * NN; idx += GRID * THREADS) {
            int b = idx / NN, m = idx - b * NN;
            const float* G = g_grad + (size_t)b * NN * 12;
            float a0 = 0.f, a1 = 0.f, a2 = 0.f;
#pragma unroll
            for (int k = 0; k < 4; ++k) {
                int n = m + 2 - k;
                if (n >= 0 && n < NN) {
                    const float* g = G + ((size_t)n * 4 + k) * 3;
                    a0 += g[0]; a1 += g[1]; a2 += g[2];
                }
            }
            if (m == 0) {
                a0 += G[0] + G[3] + G[12];
                a1 += G[1] + G[4] + G[13];
                a2 += G[2] + G[5] + G[14];
            }
            if (m == NN - 1) {
                const float* g = G + (((size_t)(NN - 1)) * 4 + 3) * 3;
                a0 += g[0]; a1 += g[1]; a2 += g[2];
            }
            float* p = out + (size_t)idx * 3;
            p[0] += s * a0; p[1] += s * a1; p[2] += s * a2;
        }
        if (step < 3) grid_bar();
        s *= 0.95f;
    }
}

// ================= launch =================
extern "C" void kernel_launch(void* const* d_in, const int* in_sizes, int n_in,
                              void* d_out, int out_size)
{
    const float* pcl = (const float*)d_in[0];
    const float* Wf1 = (const float*)d_in[1];
    const float* bf1 = (const float*)d_in[2];
    const float* Wf2 = (const float*)d_in[3];
    const float* bf2 = (const float*)d_in[4];
    const float* W0  = (const float*)d_in[5];
    const float* b0  = (const float*)d_in[6];
    const float* Wb  = (const float*)d_in[7];
    const float* bb  = (const float*)d_in[8];
    const float* Wo  = (const float*)d_in[9];
    const float* bo  = (const float*)d_in[10];
    float* out = (float*)d_out;

    cudaFuncSetAttribute(fused_denoise, cudaFuncAttributeMaxDynamicSharedMemorySize, SMEM_TOTAL);
    fused_denoise<<<GRID, THREADS, SMEM_TOTAL>>>(pcl, Wf1, bf1, Wf2, bf2, W0, b0,
                                                 Wb, bb, Wo, bo, out);
}